// round 1
// baseline (speedup 1.0000x reference)
#include <cuda_runtime.h>
#include <cuda_bf16.h>
#include <cstdint>

// Problem constants
#define Ecfg   2048
#define Hcfg   16
#define Dcfg   128
#define Bcfg   4
#define Ncfg   2048
#define QKVN   (Ecfg + 2 * Dcfg)   // 2304
#define Mrows  (Bcfg * Ncfg)       // 8192

// Scratch (allocation-free rule: __device__ globals)
__device__ float g_qkv[(size_t)Mrows * QKVN];   // 75.5 MB
__device__ float g_attn[(size_t)Mrows * Ecfg];  // 67 MB

// ---------------------------------------------------------------------------
// SGEMM + bias: C[M x Ncols] = A[M x K] * B[K x Ncols] + bias[Ncols]
// 128x128 block tile, BK=8, 256 threads, 8x8 per thread (split 4+4).
// ---------------------------------------------------------------------------
__global__ __launch_bounds__(256) void sgemm_bias(
    const float* __restrict__ A, const float* __restrict__ B,
    const float* __restrict__ bias, float* __restrict__ C,
    int M, int Ncols, int K)
{
    __shared__ float As[8][132];   // [k][row], padded: conflict-free transpose stores
    __shared__ float Bs[8][132];   // [k][col]

    const int tid = threadIdx.x;
    const int tx = tid & 15;
    const int ty = tid >> 4;
    const int bn = blockIdx.x * 128;
    const int bm = blockIdx.y * 128;

    float acc[8][8];
#pragma unroll
    for (int i = 0; i < 8; i++)
#pragma unroll
        for (int j = 0; j < 8; j++) acc[i][j] = 0.f;

    const int arow = tid >> 1;         // 0..127
    const int acol = (tid & 1) * 4;    // 0 or 4
    const int brow = tid >> 5;         // 0..7
    const int bcol = (tid & 31) * 4;   // 0..124

    const float* Aptr = A + (size_t)(bm + arow) * K + acol;
    const float* Bptr = B + (size_t)brow * Ncols + bn + bcol;

    for (int k0 = 0; k0 < K; k0 += 8) {
        const float4 av = *(const float4*)(Aptr + k0);
        const float4 bv = *(const float4*)(Bptr + (size_t)k0 * Ncols);
        __syncthreads();
        As[acol + 0][arow] = av.x;
        As[acol + 1][arow] = av.y;
        As[acol + 2][arow] = av.z;
        As[acol + 3][arow] = av.w;
        *(float4*)&Bs[brow][bcol] = bv;
        __syncthreads();

#pragma unroll
        for (int k = 0; k < 8; k++) {
            const float4 a0 = *(const float4*)&As[k][4 * ty];
            const float4 a1 = *(const float4*)&As[k][64 + 4 * ty];
            const float4 b0 = *(const float4*)&Bs[k][4 * tx];
            const float4 b1 = *(const float4*)&Bs[k][64 + 4 * tx];
            const float a[8] = {a0.x, a0.y, a0.z, a0.w, a1.x, a1.y, a1.z, a1.w};
            const float b8[8] = {b0.x, b0.y, b0.z, b0.w, b1.x, b1.y, b1.z, b1.w};
#pragma unroll
            for (int i = 0; i < 8; i++)
#pragma unroll
                for (int j = 0; j < 8; j++) acc[i][j] += a[i] * b8[j];
        }
    }

    // epilogue
#pragma unroll
    for (int i = 0; i < 8; i++) {
        const int row = bm + ((i < 4) ? (4 * ty + i) : (64 + 4 * ty + (i - 4)));
        float* crow = C + (size_t)row * Ncols;
#pragma unroll
        for (int jh = 0; jh < 2; jh++) {
            const int col = bn + (jh ? (64 + 4 * tx) : (4 * tx));
            float4 r;
            r.x = acc[i][jh * 4 + 0] + bias[col + 0];
            r.y = acc[i][jh * 4 + 1] + bias[col + 1];
            r.z = acc[i][jh * 4 + 2] + bias[col + 2];
            r.w = acc[i][jh * 4 + 3] + bias[col + 3];
            *(float4*)(crow + col) = r;
        }
    }
}

// ---------------------------------------------------------------------------
// Causal multi-query flash attention.
// Grid: (N/64, H, B); 256 threads. Tiles 64x128 in dynamic smem (LD=132 pad).
// Thread map (tx=tid&15, ty=tid>>4):
//   S phase:  rows i = 4*ty+ii (ii<4), cols j = tx + 16*jj (jj<4)
//   PV phase: rows i = 4*ty+ii,        cols c = tx + 16*cc (cc<8)
// ---------------------------------------------------------------------------
#define FTILE 64
#define FLD   132
#define SLD   65
#define FLASH_SMEM ((3 * FTILE * FLD + FTILE * SLD + 3 * FTILE) * 4)

__global__ __launch_bounds__(256) void flash_mqa_kernel(
    const float* __restrict__ qkv, float* __restrict__ outb)
{
    extern __shared__ float sm[];
    float* Qs   = sm;                       // [64][132]
    float* Ks   = Qs + FTILE * FLD;         // [64][132]
    float* Vs   = Ks + FTILE * FLD;         // [64][132]
    float* Ssh  = Vs + FTILE * FLD;         // [64][65]
    float* m_sh = Ssh + FTILE * SLD;        // [64]
    float* l_sh = m_sh + FTILE;             // [64]
    float* c_sh = l_sh + FTILE;             // [64] (rescale factor)

    const int tid = threadIdx.x;
    const int tx = tid & 15;
    const int ty = tid >> 4;
    const int qblk = blockIdx.x;
    const int h = blockIdx.y;
    const int b = blockIdx.z;
    const int q0 = qblk * FTILE;

    const float* qbase = qkv + (size_t)b * Ncfg * QKVN + h * Dcfg;
    const float* kbase = qkv + (size_t)b * Ncfg * QKVN + Ecfg;
    const float* vbase = kbase + Dcfg;
    const float SCALE = 0.08838834764831845f;  // 1/sqrt(128)

    // Load Q tile (coalesced: one 512B row per warp step)
#pragma unroll
    for (int s = 0; s < 8; s++) {
        const int idx = tid + 256 * s;
        const int r = idx >> 5, c4 = idx & 31;
        *(float4*)(Qs + r * FLD + c4 * 4) =
            *(const float4*)(qbase + (size_t)(q0 + r) * QKVN + c4 * 4);
    }
    if (tid < FTILE) {
        m_sh[tid] = __int_as_float(0xff800000);  // -inf
        l_sh[tid] = 0.f;
    }

    float acc[4][8];
#pragma unroll
    for (int i = 0; i < 4; i++)
#pragma unroll
        for (int j = 0; j < 8; j++) acc[i][j] = 0.f;

    const int nkv = qblk + 1;
    for (int kb = 0; kb < nkv; kb++) {
        const int k0 = kb * FTILE;
        __syncthreads();  // prev PV done; Q visible on first iter
#pragma unroll
        for (int s = 0; s < 8; s++) {
            const int idx = tid + 256 * s;
            const int r = idx >> 5, c4 = idx & 31;
            *(float4*)(Ks + r * FLD + c4 * 4) =
                *(const float4*)(kbase + (size_t)(k0 + r) * QKVN + c4 * 4);
            *(float4*)(Vs + r * FLD + c4 * 4) =
                *(const float4*)(vbase + (size_t)(k0 + r) * QKVN + c4 * 4);
        }
        __syncthreads();

        // S = scale * Q K^T
        float s4[4][4];
#pragma unroll
        for (int i = 0; i < 4; i++)
#pragma unroll
            for (int j = 0; j < 4; j++) s4[i][j] = 0.f;

        for (int d = 0; d < Dcfg; d += 4) {
            float4 qv[4], kv[4];
#pragma unroll
            for (int ii = 0; ii < 4; ii++)
                qv[ii] = *(const float4*)(Qs + (4 * ty + ii) * FLD + d);
#pragma unroll
            for (int jj = 0; jj < 4; jj++)
                kv[jj] = *(const float4*)(Ks + (tx + 16 * jj) * FLD + d);
#pragma unroll
            for (int ii = 0; ii < 4; ii++)
#pragma unroll
                for (int jj = 0; jj < 4; jj++) {
                    s4[ii][jj] += qv[ii].x * kv[jj].x;
                    s4[ii][jj] += qv[ii].y * kv[jj].y;
                    s4[ii][jj] += qv[ii].z * kv[jj].z;
                    s4[ii][jj] += qv[ii].w * kv[jj].w;
                }
        }
#pragma unroll
        for (int ii = 0; ii < 4; ii++)
#pragma unroll
            for (int jj = 0; jj < 4; jj++)
                Ssh[(4 * ty + ii) * SLD + tx + 16 * jj] = s4[ii][jj] * SCALE;
        __syncthreads();

        // Online softmax per row (64 threads)
        if (tid < FTILE) {
            const int i = tid;
            const int jmax = (kb < qblk) ? FTILE : (i + 1);  // causal
            float* srow = Ssh + i * SLD;
            float mx = m_sh[i];
            for (int j = 0; j < jmax; j++) mx = fmaxf(mx, srow[j]);
            const float rescale = __expf(m_sh[i] - mx);
            float sum = 0.f;
            for (int j = 0; j < jmax; j++) {
                const float p = __expf(srow[j] - mx);
                srow[j] = p;
                sum += p;
            }
            for (int j = jmax; j < FTILE; j++) srow[j] = 0.f;
            l_sh[i] = l_sh[i] * rescale + sum;
            m_sh[i] = mx;
            c_sh[i] = rescale;
        }
        __syncthreads();

        // O = O * rescale + P @ V
        float scl[4];
#pragma unroll
        for (int ii = 0; ii < 4; ii++) scl[ii] = c_sh[4 * ty + ii];
#pragma unroll
        for (int ii = 0; ii < 4; ii++)
#pragma unroll
            for (int cc = 0; cc < 8; cc++) acc[ii][cc] *= scl[ii];

#pragma unroll 2
        for (int kk = 0; kk < FTILE; kk++) {
            float p[4];
#pragma unroll
            for (int ii = 0; ii < 4; ii++) p[ii] = Ssh[(4 * ty + ii) * SLD + kk];
            float vv[8];
#pragma unroll
            for (int cc = 0; cc < 8; cc++) vv[cc] = Vs[kk * FLD + tx + 16 * cc];
#pragma unroll
            for (int ii = 0; ii < 4; ii++)
#pragma unroll
                for (int cc = 0; cc < 8; cc++) acc[ii][cc] += p[ii] * vv[cc];
        }
    }

    // epilogue: divide by l, write to (B*N, E) row-major at col h*D + c
    float linv[4];
#pragma unroll
    for (int ii = 0; ii < 4; ii++) linv[ii] = 1.f / l_sh[4 * ty + ii];
#pragma unroll
    for (int ii = 0; ii < 4; ii++) {
        float* orow = outb + (size_t)(b * Ncfg + q0 + 4 * ty + ii) * Ecfg + h * Dcfg;
#pragma unroll
        for (int cc = 0; cc < 8; cc++)
            orow[tx + 16 * cc] = acc[ii][cc] * linv[ii];
    }
}

// ---------------------------------------------------------------------------
extern "C" void kernel_launch(void* const* d_in, const int* in_sizes, int n_in,
                              void* d_out, int out_size)
{
    const float* x     = (const float*)d_in[0];
    const float* w_qkv = (const float*)d_in[1];
    const float* b_qkv = (const float*)d_in[2];
    const float* w_fc  = (const float*)d_in[3];
    const float* b_fc  = (const float*)d_in[4];
    float* out = (float*)d_out;

    float *qkv_ptr = nullptr, *attn_ptr = nullptr;
    cudaGetSymbolAddress((void**)&qkv_ptr, g_qkv);
    cudaGetSymbolAddress((void**)&attn_ptr, g_attn);

    // 1) qkv = x @ w_qkv + b_qkv   (8192 x 2304, K=2048)
    sgemm_bias<<<dim3(QKVN / 128, Mrows / 128), 256>>>(
        x, w_qkv, b_qkv, qkv_ptr, Mrows, QKVN, Ecfg);

    // 2) causal MQA flash attention -> g_attn (8192 x 2048)
    cudaFuncSetAttribute(flash_mqa_kernel,
                         cudaFuncAttributeMaxDynamicSharedMemorySize, FLASH_SMEM);
    flash_mqa_kernel<<<dim3(Ncfg / FTILE, Hcfg, Bcfg), 256, FLASH_SMEM>>>(
        qkv_ptr, attn_ptr);

    // 3) out = attn @ w_fc + b_fc  (8192 x 2048, K=2048)
    sgemm_bias<<<dim3(Ecfg / 128, Mrows / 128), 256>>>(
        attn_ptr, w_fc, b_fc, out, Mrows, Ecfg, Ecfg);
}

// round 3
// speedup vs baseline: 1.9597x; 1.9597x over previous
#include <cuda_runtime.h>
#include <cuda_bf16.h>
#include <cstdint>

// Problem constants
#define Ecfg   2048
#define Hcfg   16
#define Dcfg   128
#define Bcfg   4
#define Ncfg   2048
#define QKVN   (Ecfg + 2 * Dcfg)   // 2304
#define Mrows  (Bcfg * Ncfg)       // 8192

// Scratch (allocation-free rule: __device__ globals)
__device__ float g_qkv[(size_t)Mrows * QKVN];   // 75.5 MB
__device__ float g_attn[(size_t)Mrows * Ecfg];  // 67 MB

// ---------------------------------------------------------------------------
// tf32 warp MMA helpers (portable PTX, works on base sm_103 target)
// ---------------------------------------------------------------------------
__device__ __forceinline__ uint32_t f2tf32(float x) {
    uint32_t u;
    asm("cvt.rna.tf32.f32 %0, %1;" : "=r"(u) : "f"(x));
    return u;
}
__device__ __forceinline__ void mma16n8k8(float* d, const uint32_t* a, const uint32_t* b) {
    asm volatile(
        "mma.sync.aligned.m16n8k8.row.col.f32.tf32.tf32.f32 "
        "{%0,%1,%2,%3}, {%4,%5,%6,%7}, {%8,%9}, {%0,%1,%2,%3};\n"
        : "+f"(d[0]), "+f"(d[1]), "+f"(d[2]), "+f"(d[3])
        : "r"(a[0]), "r"(a[1]), "r"(a[2]), "r"(a[3]), "r"(b[0]), "r"(b[1]));
}

// ---------------------------------------------------------------------------
// tf32 tensor-core GEMM + bias: C[M x Ncols] = A[M x K] * W[K x Ncols] + bias
// BM=128, BN=128, BK=32. 256 threads / 8 warps; warp tile 32x64.
// A staged [m][k] LD=36 (conflict-free frags), B staged [k][n] LD=136.
// Double-buffered, one __syncthreads per chunk, LDG prefetch overlaps MMA.
// ---------------------------------------------------------------------------
#define LDA   36
#define LDB   136
#define ASZ   (128 * LDA)              // 4608 u32
#define BSZ   (32 * LDB)               // 4352 u32
#define GEMM_SMEM ((ASZ + BSZ) * 2 * 4)  // 71680 B

__global__ __launch_bounds__(256) void gemm_mma(
    const float* __restrict__ A, const float* __restrict__ W,
    const float* __restrict__ bias, float* __restrict__ C,
    int Ncols, int K)
{
    extern __shared__ uint32_t smem_u[];
    uint32_t* As[2] = { smem_u,              smem_u + ASZ + BSZ };
    uint32_t* Bs[2] = { smem_u + ASZ,        smem_u + 2 * ASZ + BSZ };

    const int tid = threadIdx.x;
    const int lane = tid & 31;
    const int wid = tid >> 5;
    const int warp_m = wid & 3;        // 4 warps along M (32 rows each)
    const int warp_n = wid >> 2;       // 2 warps along N (64 cols each)
    const int g = lane >> 2;           // 0..7
    const int tg = lane & 3;           // 0..3
    const int bm = blockIdx.y * 128;
    const int bn = blockIdx.x * 128;

    // LDG assignments
    const int a_r = tid >> 3;          // 0..31 (+32*s)
    const int a_c = (tid & 7) * 4;     // 0..28
    const int b_r = (tid >> 5) * 4;    // 0..28 (+s)
    const int b_c = (lane) * 4;        // 0..124

    const float* Ab = A + (size_t)bm * K;
    const float* Wb = W + bn;

    float4 ar[4], br[4];
    float acc[2][8][4];
#pragma unroll
    for (int mt = 0; mt < 2; mt++)
#pragma unroll
        for (int nt = 0; nt < 8; nt++)
#pragma unroll
            for (int j = 0; j < 4; j++) acc[mt][nt][j] = 0.f;

#define LDG_CHUNK(k0) do { \
    _Pragma("unroll") for (int s = 0; s < 4; s++) \
        ar[s] = *(const float4*)(Ab + (size_t)(a_r + 32 * s) * K + (k0) + a_c); \
    _Pragma("unroll") for (int s = 0; s < 4; s++) \
        br[s] = *(const float4*)(Wb + (size_t)((k0) + b_r + s) * Ncols + b_c); \
    } while (0)

#define STS_CHUNK(buf) do { \
    uint32_t* Ad = As[buf]; uint32_t* Bd = Bs[buf]; \
    _Pragma("unroll") for (int s = 0; s < 4; s++) { \
        uint32_t* p = Ad + (a_r + 32 * s) * LDA + a_c; \
        p[0] = f2tf32(ar[s].x); p[1] = f2tf32(ar[s].y); \
        p[2] = f2tf32(ar[s].z); p[3] = f2tf32(ar[s].w); } \
    _Pragma("unroll") for (int s = 0; s < 4; s++) { \
        uint32_t* p = Bd + (b_r + s) * LDB + b_c; \
        p[0] = f2tf32(br[s].x); p[1] = f2tf32(br[s].y); \
        p[2] = f2tf32(br[s].z); p[3] = f2tf32(br[s].w); } \
    } while (0)

#define MMA_CHUNK(buf) do { \
    const uint32_t* Ad = As[buf]; const uint32_t* Bd = Bs[buf]; \
    _Pragma("unroll") for (int ks = 0; ks < 4; ks++) { \
        uint32_t afr[2][4], bfr[8][2]; \
        _Pragma("unroll") for (int mt = 0; mt < 2; mt++) { \
            const int mr = warp_m * 32 + mt * 16; \
            afr[mt][0] = Ad[(mr + g)     * LDA + ks * 8 + tg]; \
            afr[mt][1] = Ad[(mr + g + 8) * LDA + ks * 8 + tg]; \
            afr[mt][2] = Ad[(mr + g)     * LDA + ks * 8 + tg + 4]; \
            afr[mt][3] = Ad[(mr + g + 8) * LDA + ks * 8 + tg + 4]; } \
        _Pragma("unroll") for (int nt = 0; nt < 8; nt++) { \
            const int nc = warp_n * 64 + nt * 8; \
            bfr[nt][0] = Bd[(ks * 8 + tg)     * LDB + nc + g]; \
            bfr[nt][1] = Bd[(ks * 8 + tg + 4) * LDB + nc + g]; } \
        _Pragma("unroll") for (int mt = 0; mt < 2; mt++) \
            _Pragma("unroll") for (int nt = 0; nt < 8; nt++) \
                mma16n8k8(acc[mt][nt], afr[mt], bfr[nt]); \
    } } while (0)

    const int NCHUNK = K / 32;
    LDG_CHUNK(0);
    STS_CHUNK(0);
    __syncthreads();

    for (int c = 0; c < NCHUNK; c++) {
        const int cur = c & 1;
        if (c + 1 < NCHUNK) LDG_CHUNK((c + 1) * 32);
        MMA_CHUNK(cur);
        if (c + 1 < NCHUNK) {
            STS_CHUNK(cur ^ 1);
            __syncthreads();
        }
    }

    // Epilogue: d0,d1 -> (row g, cols 2tg,2tg+1); d2,d3 -> row g+8
#pragma unroll
    for (int mt = 0; mt < 2; mt++) {
        const int row0 = bm + warp_m * 32 + mt * 16 + g;
#pragma unroll
        for (int nt = 0; nt < 8; nt++) {
            const int col = bn + warp_n * 64 + nt * 8 + 2 * tg;
            const float bx = __ldg(&bias[col]);
            const float by = __ldg(&bias[col + 1]);
            float2 v0 = { acc[mt][nt][0] + bx, acc[mt][nt][1] + by };
            float2 v1 = { acc[mt][nt][2] + bx, acc[mt][nt][3] + by };
            *(float2*)(C + (size_t)row0 * Ncols + col) = v0;
            *(float2*)(C + (size_t)(row0 + 8) * Ncols + col) = v1;
        }
    }
}

// ---------------------------------------------------------------------------
// Causal multi-query flash attention (fp32, unchanged from round 1).
// ---------------------------------------------------------------------------
#define FTILE 64
#define FLD   132
#define SLD   65
#define FLASH_SMEM ((3 * FTILE * FLD + FTILE * SLD + 3 * FTILE) * 4)

__global__ __launch_bounds__(256) void flash_mqa_kernel(
    const float* __restrict__ qkv, float* __restrict__ outb)
{
    extern __shared__ float sm[];
    float* Qs   = sm;
    float* Ks   = Qs + FTILE * FLD;
    float* Vs   = Ks + FTILE * FLD;
    float* Ssh  = Vs + FTILE * FLD;
    float* m_sh = Ssh + FTILE * SLD;
    float* l_sh = m_sh + FTILE;
    float* c_sh = l_sh + FTILE;

    const int tid = threadIdx.x;
    const int tx = tid & 15;
    const int ty = tid >> 4;
    const int qblk = blockIdx.x;
    const int h = blockIdx.y;
    const int b = blockIdx.z;
    const int q0 = qblk * FTILE;

    const float* qbase = qkv + (size_t)b * Ncfg * QKVN + h * Dcfg;
    const float* kbase = qkv + (size_t)b * Ncfg * QKVN + Ecfg;
    const float* vbase = kbase + Dcfg;
    const float SCALE = 0.08838834764831845f;

#pragma unroll
    for (int s = 0; s < 8; s++) {
        const int idx = tid + 256 * s;
        const int r = idx >> 5, c4 = idx & 31;
        *(float4*)(Qs + r * FLD + c4 * 4) =
            *(const float4*)(qbase + (size_t)(q0 + r) * QKVN + c4 * 4);
    }
    if (tid < FTILE) {
        m_sh[tid] = __int_as_float(0xff800000);
        l_sh[tid] = 0.f;
    }

    float acc[4][8];
#pragma unroll
    for (int i = 0; i < 4; i++)
#pragma unroll
        for (int j = 0; j < 8; j++) acc[i][j] = 0.f;

    const int nkv = qblk + 1;
    for (int kb = 0; kb < nkv; kb++) {
        const int k0 = kb * FTILE;
        __syncthreads();
#pragma unroll
        for (int s = 0; s < 8; s++) {
            const int idx = tid + 256 * s;
            const int r = idx >> 5, c4 = idx & 31;
            *(float4*)(Ks + r * FLD + c4 * 4) =
                *(const float4*)(kbase + (size_t)(k0 + r) * QKVN + c4 * 4);
            *(float4*)(Vs + r * FLD + c4 * 4) =
                *(const float4*)(vbase + (size_t)(k0 + r) * QKVN + c4 * 4);
        }
        __syncthreads();

        float s4[4][4];
#pragma unroll
        for (int i = 0; i < 4; i++)
#pragma unroll
            for (int j = 0; j < 4; j++) s4[i][j] = 0.f;

        for (int d = 0; d < Dcfg; d += 4) {
            float4 qv[4], kv[4];
#pragma unroll
            for (int ii = 0; ii < 4; ii++)
                qv[ii] = *(const float4*)(Qs + (4 * ty + ii) * FLD + d);
#pragma unroll
            for (int jj = 0; jj < 4; jj++)
                kv[jj] = *(const float4*)(Ks + (tx + 16 * jj) * FLD + d);
#pragma unroll
            for (int ii = 0; ii < 4; ii++)
#pragma unroll
                for (int jj = 0; jj < 4; jj++) {
                    s4[ii][jj] += qv[ii].x * kv[jj].x;
                    s4[ii][jj] += qv[ii].y * kv[jj].y;
                    s4[ii][jj] += qv[ii].z * kv[jj].z;
                    s4[ii][jj] += qv[ii].w * kv[jj].w;
                }
        }
#pragma unroll
        for (int ii = 0; ii < 4; ii++)
#pragma unroll
            for (int jj = 0; jj < 4; jj++)
                Ssh[(4 * ty + ii) * SLD + tx + 16 * jj] = s4[ii][jj] * SCALE;
        __syncthreads();

        if (tid < FTILE) {
            const int i = tid;
            const int jmax = (kb < qblk) ? FTILE : (i + 1);
            float* srow = Ssh + i * SLD;
            float mx = m_sh[i];
            for (int j = 0; j < jmax; j++) mx = fmaxf(mx, srow[j]);
            const float rescale = __expf(m_sh[i] - mx);
            float sum = 0.f;
            for (int j = 0; j < jmax; j++) {
                const float p = __expf(srow[j] - mx);
                srow[j] = p;
                sum += p;
            }
            for (int j = jmax; j < FTILE; j++) srow[j] = 0.f;
            l_sh[i] = l_sh[i] * rescale + sum;
            m_sh[i] = mx;
            c_sh[i] = rescale;
        }
        __syncthreads();

        float scl[4];
#pragma unroll
        for (int ii = 0; ii < 4; ii++) scl[ii] = c_sh[4 * ty + ii];
#pragma unroll
        for (int ii = 0; ii < 4; ii++)
#pragma unroll
            for (int cc = 0; cc < 8; cc++) acc[ii][cc] *= scl[ii];

#pragma unroll 2
        for (int kk = 0; kk < FTILE; kk++) {
            float p[4];
#pragma unroll
            for (int ii = 0; ii < 4; ii++) p[ii] = Ssh[(4 * ty + ii) * SLD + kk];
            float vv[8];
#pragma unroll
            for (int cc = 0; cc < 8; cc++) vv[cc] = Vs[kk * FLD + tx + 16 * cc];
#pragma unroll
            for (int ii = 0; ii < 4; ii++)
#pragma unroll
                for (int cc = 0; cc < 8; cc++) acc[ii][cc] += p[ii] * vv[cc];
        }
    }

    float linv[4];
#pragma unroll
    for (int ii = 0; ii < 4; ii++) linv[ii] = 1.f / l_sh[4 * ty + ii];
#pragma unroll
    for (int ii = 0; ii < 4; ii++) {
        float* orow = outb + (size_t)(b * Ncfg + q0 + 4 * ty + ii) * Ecfg + h * Dcfg;
#pragma unroll
        for (int cc = 0; cc < 8; cc++)
            orow[tx + 16 * cc] = acc[ii][cc] * linv[ii];
    }
}

// ---------------------------------------------------------------------------
extern "C" void kernel_launch(void* const* d_in, const int* in_sizes, int n_in,
                              void* d_out, int out_size)
{
    const float* x     = (const float*)d_in[0];
    const float* w_qkv = (const float*)d_in[1];
    const float* b_qkv = (const float*)d_in[2];
    const float* w_fc  = (const float*)d_in[3];
    const float* b_fc  = (const float*)d_in[4];
    float* out = (float*)d_out;

    float *qkv_ptr, *attn_ptr;
    cudaGetSymbolAddress((void**)&qkv_ptr, g_qkv);
    cudaGetSymbolAddress((void**)&attn_ptr, g_attn);

    cudaFuncSetAttribute(gemm_mma, cudaFuncAttributeMaxDynamicSharedMemorySize, GEMM_SMEM);
    cudaFuncSetAttribute(flash_mqa_kernel, cudaFuncAttributeMaxDynamicSharedMemorySize, FLASH_SMEM);

    // 1) qkv = x @ w_qkv + b_qkv   (8192 x 2304, K=2048)
    gemm_mma<<<dim3(QKVN / 128, Mrows / 128), 256, GEMM_SMEM>>>(
        x, w_qkv, b_qkv, qkv_ptr, QKVN, Ecfg);

    // 2) causal MQA flash attention -> g_attn (8192 x 2048)
    flash_mqa_kernel<<<dim3(Ncfg / FTILE, Hcfg, Bcfg), 256, FLASH_SMEM>>>(
        qkv_ptr, attn_ptr);

    // 3) out = attn @ w_fc + b_fc  (8192 x 2048, K=2048)
    gemm_mma<<<dim3(Ecfg / 128, Mrows / 128), 256, GEMM_SMEM>>>(
        attn_ptr, w_fc, b_fc, out, Ecfg, Ecfg);
}

// round 4
// speedup vs baseline: 5.6866x; 2.9018x over previous
#include <cuda_runtime.h>
#include <cuda_bf16.h>
#include <cstdint>

// Problem constants
#define Ecfg   2048
#define Hcfg   16
#define Dcfg   128
#define Bcfg   4
#define Ncfg   2048
#define QKVN   (Ecfg + 2 * Dcfg)   // 2304
#define Mrows  (Bcfg * Ncfg)       // 8192

// Scratch (allocation-free rule: __device__ globals)
__device__ float g_qkv[(size_t)Mrows * QKVN];   // 75.5 MB
__device__ float g_attn[(size_t)Mrows * Ecfg];  // 67 MB

// ---------------------------------------------------------------------------
// helpers
// ---------------------------------------------------------------------------
__device__ __forceinline__ uint32_t f2tf32(float x) {
    uint32_t u;
    asm("cvt.rna.tf32.f32 %0, %1;" : "=r"(u) : "f"(x));
    return u;
}
__device__ __forceinline__ float ex2(float x) {
    float y;
    asm("ex2.approx.ftz.f32 %0, %1;" : "=f"(y) : "f"(x));
    return y;
}
__device__ __forceinline__ void mma16n8k8(float* d, const uint32_t* a, const uint32_t* b) {
    asm volatile(
        "mma.sync.aligned.m16n8k8.row.col.f32.tf32.tf32.f32 "
        "{%0,%1,%2,%3}, {%4,%5,%6,%7}, {%8,%9}, {%0,%1,%2,%3};\n"
        : "+f"(d[0]), "+f"(d[1]), "+f"(d[2]), "+f"(d[3])
        : "r"(a[0]), "r"(a[1]), "r"(a[2]), "r"(a[3]), "r"(b[0]), "r"(b[1]));
}
__device__ __forceinline__ uint32_t smem_u32(const void* p) {
    uint32_t a;
    asm("{ .reg .u64 t; cvta.to.shared.u64 t, %1; cvt.u32.u64 %0, t; }" : "=r"(a) : "l"(p));
    return a;
}
#define CP_ASYNC16(sa, gp) \
    asm volatile("cp.async.cg.shared.global [%0], [%1], 16;" :: "r"(sa), "l"(gp))
#define CP_COMMIT() asm volatile("cp.async.commit_group;" ::: "memory")
#define CP_WAIT(n)  asm volatile("cp.async.wait_group %0;" :: "n"(n) : "memory")

// ---------------------------------------------------------------------------
// tf32 tensor-core GEMM + bias: C[M x Ncols] = A[M x K] * W[K x Ncols] + bias
// BM=128, BN=128, BK=32. 256 threads / 8 warps; warp tile 32x64.
// 2-stage cp.async pipeline (raw fp32 in smem, cvt.rna at fragment load),
// 2 CTAs/SM.
// ---------------------------------------------------------------------------
#define LDA   36
#define LDB   136
#define ASZ   (128 * LDA)                 // 4608 u32
#define BSZ   (32 * LDB)                  // 4352 u32
#define STG   (ASZ + BSZ)                 // u32 per stage
#define GEMM_SMEM (STG * 2 * 4)           // 71680 B

__global__ __launch_bounds__(256, 2) void gemm_mma(
    const float* __restrict__ A, const float* __restrict__ W,
    const float* __restrict__ bias, float* __restrict__ C,
    int Ncols, int K)
{
    extern __shared__ uint32_t smem_u[];
    const uint32_t sbase = smem_u32(smem_u);

    const int tid = threadIdx.x;
    const int lane = tid & 31;
    const int wid = tid >> 5;
    const int warp_m = wid & 3;
    const int warp_n = wid >> 2;
    const int g = lane >> 2;
    const int tg = lane & 3;
    const int bm = blockIdx.y * 128;
    const int bn = blockIdx.x * 128;

    const int a_r = tid >> 3;          // 0..31 (+32*s)
    const int a_c = (tid & 7) * 4;     // 0..28
    const int b_r = (tid >> 5) * 4;    // 0..28 (+s)
    const int b_c = lane * 4;          // 0..124

    const float* Ab = A + (size_t)bm * K;
    const float* Wb = W + bn;

    float acc[2][8][4];
#pragma unroll
    for (int mt = 0; mt < 2; mt++)
#pragma unroll
        for (int nt = 0; nt < 8; nt++)
#pragma unroll
            for (int j = 0; j < 4; j++) acc[mt][nt][j] = 0.f;

#define CPA_CHUNK(buf, k0) do { \
    const uint32_t so = sbase + (uint32_t)(buf) * (STG * 4); \
    _Pragma("unroll") for (int s = 0; s < 4; s++) \
        CP_ASYNC16(so + ((a_r + 32 * s) * LDA + a_c) * 4, \
                   Ab + (size_t)(a_r + 32 * s) * K + (k0) + a_c); \
    _Pragma("unroll") for (int s = 0; s < 4; s++) \
        CP_ASYNC16(so + (ASZ + (b_r + s) * LDB + b_c) * 4, \
                   Wb + (size_t)((k0) + b_r + s) * Ncols + b_c); \
    CP_COMMIT(); \
    } while (0)

#define MMA_CHUNK(buf) do { \
    const uint32_t* Ad = smem_u + (buf) * STG; \
    const uint32_t* Bd = Ad + ASZ; \
    _Pragma("unroll") for (int ks = 0; ks < 4; ks++) { \
        uint32_t afr[2][4], bfr[8][2]; \
        _Pragma("unroll") for (int mt = 0; mt < 2; mt++) { \
            const int mr = warp_m * 32 + mt * 16; \
            afr[mt][0] = f2tf32(__uint_as_float(Ad[(mr + g)     * LDA + ks * 8 + tg])); \
            afr[mt][1] = f2tf32(__uint_as_float(Ad[(mr + g + 8) * LDA + ks * 8 + tg])); \
            afr[mt][2] = f2tf32(__uint_as_float(Ad[(mr + g)     * LDA + ks * 8 + tg + 4])); \
            afr[mt][3] = f2tf32(__uint_as_float(Ad[(mr + g + 8) * LDA + ks * 8 + tg + 4])); } \
        _Pragma("unroll") for (int nt = 0; nt < 8; nt++) { \
            const int nc = warp_n * 64 + nt * 8; \
            bfr[nt][0] = f2tf32(__uint_as_float(Bd[(ks * 8 + tg)     * LDB + nc + g])); \
            bfr[nt][1] = f2tf32(__uint_as_float(Bd[(ks * 8 + tg + 4) * LDB + nc + g])); } \
        _Pragma("unroll") for (int mt = 0; mt < 2; mt++) \
            _Pragma("unroll") for (int nt = 0; nt < 8; nt++) \
                mma16n8k8(acc[mt][nt], afr[mt], bfr[nt]); \
    } } while (0)

    const int NCHUNK = K / 32;
    CPA_CHUNK(0, 0);

    for (int c = 0; c < NCHUNK; c++) {
        if (c + 1 < NCHUNK) {
            CPA_CHUNK((c + 1) & 1, (c + 1) * 32);
            CP_WAIT(1);
        } else {
            CP_WAIT(0);
        }
        __syncthreads();
        MMA_CHUNK(c & 1);
        __syncthreads();
    }

    // Epilogue
#pragma unroll
    for (int mt = 0; mt < 2; mt++) {
        const int row0 = bm + warp_m * 32 + mt * 16 + g;
#pragma unroll
        for (int nt = 0; nt < 8; nt++) {
            const int col = bn + warp_n * 64 + nt * 8 + 2 * tg;
            const float bx = __ldg(&bias[col]);
            const float by = __ldg(&bias[col + 1]);
            float2 v0 = { acc[mt][nt][0] + bx, acc[mt][nt][1] + by };
            float2 v1 = { acc[mt][nt][2] + bx, acc[mt][nt][3] + by };
            *(float2*)(C + (size_t)row0 * Ncols + col) = v0;
            *(float2*)(C + (size_t)(row0 + 8) * Ncols + col) = v1;
        }
    }
}

// ---------------------------------------------------------------------------
// Causal multi-query flash attention with tf32 mma.sync.
// Grid: (N/128, H, B); 256 threads / 8 warps; warp = 16 query rows.
// Q/K/V staged in smem as tf32 (LD=136 -> conflict-free fragment loads).
// Online softmax fully in registers (quad shfl reductions).
// P round-trips through smem (LD=72) so PV A-fragments need no permutes.
// ---------------------------------------------------------------------------
#define FQ   128
#define FKV  64
#define LDF  136
#define LDP  72
#define FLASH_SMEM ((FQ * LDF + 2 * FKV * LDF + FQ * LDP) * 4)   // 176128 B

__global__ __launch_bounds__(256) void flash_mma(
    const float* __restrict__ qkv, float* __restrict__ outb)
{
    extern __shared__ uint32_t smf[];
    uint32_t* Qs = smf;
    uint32_t* Ks = Qs + FQ * LDF;
    uint32_t* Vs = Ks + FKV * LDF;
    uint32_t* Ps = Vs + FKV * LDF;

    const int tid = threadIdx.x;
    const int lane = tid & 31;
    const int wid = tid >> 5;
    const int g = lane >> 2;
    const int tg = lane & 3;

    const int qb = (gridDim.x - 1) - blockIdx.x;   // heavy blocks first
    const int h = blockIdx.y;
    const int b = blockIdx.z;
    const int q0 = qb * FQ;

    const float* qbase = qkv + (size_t)b * Ncfg * QKVN + h * Dcfg;
    const float* kbase = qkv + (size_t)b * Ncfg * QKVN + Ecfg;
    const float* vbase = kbase + Dcfg;

    const float S2 = 0.08838834764831845f * 1.4426950408889634f; // scale*log2e
    const float NEG = -1e30f;

    // Stage Q (128 x 128 fp32 -> tf32)
#pragma unroll
    for (int s = 0; s < 16; s++) {
        const int idx = s * 256 + tid;
        const int r = idx >> 5, c4 = (idx & 31) * 4;
        float4 v = *(const float4*)(qbase + (size_t)(q0 + r) * QKVN + c4);
        uint4 u = { f2tf32(v.x), f2tf32(v.y), f2tf32(v.z), f2tf32(v.w) };
        *(uint4*)(Qs + r * LDF + c4) = u;
    }

    float ofr[16][4];
#pragma unroll
    for (int nt = 0; nt < 16; nt++)
#pragma unroll
        for (int j = 0; j < 4; j++) ofr[nt][j] = 0.f;
    float m0 = NEG, m1 = NEG, l0 = 0.f, l1 = 0.f;

    const int wrow = 16 * wid + g;            // local row (first of pair)
    const int row0 = q0 + wrow;
    const int row1 = row0 + 8;
    const int nkv = 2 * (qb + 1);

    for (int kb = 0; kb < nkv; kb++) {
        const int k0 = kb * FKV;
        __syncthreads();   // prev tile's S & PV reads of Ks/Vs done
        // Stage K,V (64 x 128 each)
#pragma unroll
        for (int s = 0; s < 8; s++) {
            const int idx = s * 256 + tid;
            const int r = idx >> 5, c4 = (idx & 31) * 4;
            float4 kv4 = *(const float4*)(kbase + (size_t)(k0 + r) * QKVN + c4);
            float4 vv4 = *(const float4*)(vbase + (size_t)(k0 + r) * QKVN + c4);
            uint4 ku = { f2tf32(kv4.x), f2tf32(kv4.y), f2tf32(kv4.z), f2tf32(kv4.w) };
            uint4 vu = { f2tf32(vv4.x), f2tf32(vv4.y), f2tf32(vv4.z), f2tf32(vv4.w) };
            *(uint4*)(Ks + r * LDF + c4) = ku;
            *(uint4*)(Vs + r * LDF + c4) = vu;
        }
        __syncthreads();

        // S = Q K^T  (warp: 16 rows x 64 cols)
        float sfr[8][4];
#pragma unroll
        for (int nt = 0; nt < 8; nt++)
#pragma unroll
            for (int j = 0; j < 4; j++) sfr[nt][j] = 0.f;

#pragma unroll
        for (int ks = 0; ks < 16; ks++) {
            uint32_t afr[4];
            afr[0] = Qs[(wrow)     * LDF + 8 * ks + tg];
            afr[1] = Qs[(wrow + 8) * LDF + 8 * ks + tg];
            afr[2] = Qs[(wrow)     * LDF + 8 * ks + tg + 4];
            afr[3] = Qs[(wrow + 8) * LDF + 8 * ks + tg + 4];
#pragma unroll
            for (int nt = 0; nt < 8; nt++) {
                uint32_t bfr[2];
                bfr[0] = Ks[(8 * nt + g) * LDF + 8 * ks + tg];
                bfr[1] = Ks[(8 * nt + g) * LDF + 8 * ks + tg + 4];
                mma16n8k8(sfr[nt], afr, bfr);
            }
        }

        // scale (to base-2 domain) + causal mask
#pragma unroll
        for (int nt = 0; nt < 8; nt++)
#pragma unroll
            for (int j = 0; j < 4; j++) sfr[nt][j] *= S2;

        if (kb >= nkv - 2) {
#pragma unroll
            for (int nt = 0; nt < 8; nt++) {
                const int c0 = k0 + 8 * nt + 2 * tg;
                if (c0     > row0) sfr[nt][0] = NEG;
                if (c0 + 1 > row0) sfr[nt][1] = NEG;
                if (c0     > row1) sfr[nt][2] = NEG;
                if (c0 + 1 > row1) sfr[nt][3] = NEG;
            }
        }

        // online softmax (rows row0 / row1), quad shfl reductions
        float mx0 = NEG, mx1 = NEG;
#pragma unroll
        for (int nt = 0; nt < 8; nt++) {
            mx0 = fmaxf(mx0, fmaxf(sfr[nt][0], sfr[nt][1]));
            mx1 = fmaxf(mx1, fmaxf(sfr[nt][2], sfr[nt][3]));
        }
        mx0 = fmaxf(mx0, __shfl_xor_sync(0xffffffff, mx0, 1));
        mx0 = fmaxf(mx0, __shfl_xor_sync(0xffffffff, mx0, 2));
        mx1 = fmaxf(mx1, __shfl_xor_sync(0xffffffff, mx1, 1));
        mx1 = fmaxf(mx1, __shfl_xor_sync(0xffffffff, mx1, 2));

        const float mn0 = fmaxf(m0, mx0);
        const float mn1 = fmaxf(m1, mx1);
        const float scl0 = ex2(m0 - mn0);
        const float scl1 = ex2(m1 - mn1);

        float sum0 = 0.f, sum1 = 0.f;
#pragma unroll
        for (int nt = 0; nt < 8; nt++) {
            sfr[nt][0] = ex2(sfr[nt][0] - mn0);
            sfr[nt][1] = ex2(sfr[nt][1] - mn0);
            sfr[nt][2] = ex2(sfr[nt][2] - mn1);
            sfr[nt][3] = ex2(sfr[nt][3] - mn1);
            sum0 += sfr[nt][0] + sfr[nt][1];
            sum1 += sfr[nt][2] + sfr[nt][3];
        }
        sum0 += __shfl_xor_sync(0xffffffff, sum0, 1);
        sum0 += __shfl_xor_sync(0xffffffff, sum0, 2);
        sum1 += __shfl_xor_sync(0xffffffff, sum1, 1);
        sum1 += __shfl_xor_sync(0xffffffff, sum1, 2);

        l0 = l0 * scl0 + sum0;  m0 = mn0;
        l1 = l1 * scl1 + sum1;  m1 = mn1;

        // rescale O
#pragma unroll
        for (int nt = 0; nt < 16; nt++) {
            ofr[nt][0] *= scl0; ofr[nt][1] *= scl0;
            ofr[nt][2] *= scl1; ofr[nt][3] *= scl1;
        }

        // store P (tf32) to smem — warp-local
#pragma unroll
        for (int nt = 0; nt < 8; nt++) {
            uint2 p0 = { f2tf32(sfr[nt][0]), f2tf32(sfr[nt][1]) };
            uint2 p1 = { f2tf32(sfr[nt][2]), f2tf32(sfr[nt][3]) };
            *(uint2*)(Ps + (wrow)     * LDP + 8 * nt + 2 * tg) = p0;
            *(uint2*)(Ps + (wrow + 8) * LDP + 8 * nt + 2 * tg) = p1;
        }
        __syncwarp();

        // O += P V
#pragma unroll
        for (int ks = 0; ks < 8; ks++) {
            uint32_t afr[4];
            afr[0] = Ps[(wrow)     * LDP + 8 * ks + tg];
            afr[1] = Ps[(wrow + 8) * LDP + 8 * ks + tg];
            afr[2] = Ps[(wrow)     * LDP + 8 * ks + tg + 4];
            afr[3] = Ps[(wrow + 8) * LDP + 8 * ks + tg + 4];
#pragma unroll
            for (int nt = 0; nt < 16; nt++) {
                uint32_t bfr[2];
                bfr[0] = Vs[(8 * ks + tg)     * LDF + 8 * nt + g];
                bfr[1] = Vs[(8 * ks + tg + 4) * LDF + 8 * nt + g];
                mma16n8k8(ofr[nt], afr, bfr);
            }
        }
    }

    // epilogue
    const float rl0 = 1.f / l0;
    const float rl1 = 1.f / l1;
    float* o0 = outb + (size_t)(b * Ncfg + row0) * Ecfg + h * Dcfg;
    float* o1 = outb + (size_t)(b * Ncfg + row1) * Ecfg + h * Dcfg;
#pragma unroll
    for (int nt = 0; nt < 16; nt++) {
        const int col = 8 * nt + 2 * tg;
        float2 v0 = { ofr[nt][0] * rl0, ofr[nt][1] * rl0 };
        float2 v1 = { ofr[nt][2] * rl1, ofr[nt][3] * rl1 };
        *(float2*)(o0 + col) = v0;
        *(float2*)(o1 + col) = v1;
    }
}

// ---------------------------------------------------------------------------
extern "C" void kernel_launch(void* const* d_in, const int* in_sizes, int n_in,
                              void* d_out, int out_size)
{
    const float* x     = (const float*)d_in[0];
    const float* w_qkv = (const float*)d_in[1];
    const float* b_qkv = (const float*)d_in[2];
    const float* w_fc  = (const float*)d_in[3];
    const float* b_fc  = (const float*)d_in[4];
    float* out = (float*)d_out;

    float *qkv_ptr, *attn_ptr;
    cudaGetSymbolAddress((void**)&qkv_ptr, g_qkv);
    cudaGetSymbolAddress((void**)&attn_ptr, g_attn);

    cudaFuncSetAttribute(gemm_mma, cudaFuncAttributeMaxDynamicSharedMemorySize, GEMM_SMEM);
    cudaFuncSetAttribute(flash_mma, cudaFuncAttributeMaxDynamicSharedMemorySize, FLASH_SMEM);

    // 1) qkv = x @ w_qkv + b_qkv   (8192 x 2304, K=2048)
    gemm_mma<<<dim3(QKVN / 128, Mrows / 128), 256, GEMM_SMEM>>>(
        x, w_qkv, b_qkv, qkv_ptr, QKVN, Ecfg);

    // 2) causal MQA flash attention (tensor cores) -> g_attn
    flash_mma<<<dim3(Ncfg / FQ, Hcfg, Bcfg), 256, FLASH_SMEM>>>(
        qkv_ptr, attn_ptr);

    // 3) out = attn @ w_fc + b_fc  (8192 x 2048, K=2048)
    gemm_mma<<<dim3(Ecfg / 128, Mrows / 128), 256, GEMM_SMEM>>>(
        attn_ptr, w_fc, b_fc, out, Ecfg, Ecfg);
}

// round 5
// speedup vs baseline: 6.3693x; 1.1200x over previous
#include <cuda_runtime.h>
#include <cuda_bf16.h>
#include <cstdint>

// Problem constants
#define Ecfg   2048
#define Hcfg   16
#define Dcfg   128
#define Bcfg   4
#define Ncfg   2048
#define QKVN   (Ecfg + 2 * Dcfg)   // 2304
#define Mrows  (Bcfg * Ncfg)       // 8192

// Scratch (allocation-free rule: __device__ globals)
__device__ float    g_qkv[(size_t)Mrows * QKVN];     // qkv fp32 (Q read from here)
__device__ uint32_t g_xp[(size_t)Mrows * Ecfg];      // x packed tf32
__device__ uint32_t g_wqkvp[(size_t)QKVN * Ecfg];    // w_qkv^T packed
__device__ uint32_t g_wfcp[(size_t)Ecfg * Ecfg];     // w_fc^T packed
__device__ uint32_t g_kp[(size_t)Mrows * Dcfg];      // K packed [b*N][128]
__device__ uint32_t g_vtp[(size_t)Bcfg * Dcfg * Ncfg]; // V^T packed [b][128][N]
__device__ uint32_t g_attnp[(size_t)Mrows * Ecfg];   // attn out packed tf32

// ---------------------------------------------------------------------------
// helpers
// ---------------------------------------------------------------------------
__device__ __forceinline__ uint32_t f2tf32(float x) {
    uint32_t u;
    asm("cvt.rna.tf32.f32 %0, %1;" : "=r"(u) : "f"(x));
    return u;
}
__device__ __forceinline__ float ex2(float x) {
    float y;
    asm("ex2.approx.ftz.f32 %0, %1;" : "=f"(y) : "f"(x));
    return y;
}
__device__ __forceinline__ void mma16n8k8(float* d, const uint32_t* a, const uint32_t* b) {
    asm volatile(
        "mma.sync.aligned.m16n8k8.row.col.f32.tf32.tf32.f32 "
        "{%0,%1,%2,%3}, {%4,%5,%6,%7}, {%8,%9}, {%0,%1,%2,%3};\n"
        : "+f"(d[0]), "+f"(d[1]), "+f"(d[2]), "+f"(d[3])
        : "r"(a[0]), "r"(a[1]), "r"(a[2]), "r"(a[3]), "r"(b[0]), "r"(b[1]));
}
__device__ __forceinline__ uint32_t smem_u32(const void* p) {
    uint32_t a;
    asm("{ .reg .u64 t; cvta.to.shared.u64 t, %1; cvt.u32.u64 %0, t; }" : "=r"(a) : "l"(p));
    return a;
}
#define CP_ASYNC16(sa, gp) \
    asm volatile("cp.async.cg.shared.global [%0], [%1], 16;" :: "r"(sa), "l"(gp))
#define CP_COMMIT() asm volatile("cp.async.commit_group;" ::: "memory")
#define CP_WAIT(n)  asm volatile("cp.async.wait_group %0;" :: "n"(n) : "memory")

// pack permutation within 8-group: value of original k stored at 2*(k&3) | (k>>2)&1
// -> fragment pair (tg, tg+4) lives at (2tg, 2tg+1): one LDS.64.

// ---------------------------------------------------------------------------
// prep kernel 1: elementwise fp32 -> packed tf32 (flat, groups of 8)
// ---------------------------------------------------------------------------
__global__ __launch_bounds__(256) void pack_tf32_flat(
    const float* __restrict__ src, uint32_t* __restrict__ dst, size_t n8)
{
    size_t t = (size_t)blockIdx.x * 256 + threadIdx.x;
    if (t >= n8) return;
    const float4* s = (const float4*)(src + t * 8);
    float4 a = s[0], b = s[1];
    uint4 o0 = { f2tf32(a.x), f2tf32(b.x), f2tf32(a.y), f2tf32(b.y) };
    uint4 o1 = { f2tf32(a.z), f2tf32(b.z), f2tf32(a.w), f2tf32(b.w) };
    uint4* d = (uint4*)(dst + t * 8);
    d[0] = o0; d[1] = o1;
}

// ---------------------------------------------------------------------------
// prep kernel 2: K slice of qkv -> packed [8192][128]
// ---------------------------------------------------------------------------
__global__ __launch_bounds__(256) void pack_k_kernel(
    const float* __restrict__ qkv, uint32_t* __restrict__ kp)
{
    int t = blockIdx.x * 256 + threadIdx.x;       // 8192*16
    int row = t >> 4, grp = t & 15;
    const float4* s = (const float4*)(qkv + (size_t)row * QKVN + Ecfg + grp * 8);
    float4 a = s[0], b = s[1];
    uint4 o0 = { f2tf32(a.x), f2tf32(b.x), f2tf32(a.y), f2tf32(b.y) };
    uint4 o1 = { f2tf32(a.z), f2tf32(b.z), f2tf32(a.w), f2tf32(b.w) };
    uint4* d = (uint4*)(kp + (size_t)row * Dcfg + grp * 8);
    d[0] = o0; d[1] = o1;
}

// ---------------------------------------------------------------------------
// prep kernel 3: transpose + pack:  dst[j][packed(i)] = src[i][j]
// src element (i,j) at src[i*sStride + j]; grid (NI/32, NJ/32, nz)
// ---------------------------------------------------------------------------
__global__ __launch_bounds__(256) void transpose_pack(
    const float* __restrict__ src, size_t sStride, size_t zsrc,
    uint32_t* __restrict__ dst, size_t zdst, int NI)
{
    __shared__ float t[32][33];
    src += (size_t)blockIdx.z * zsrc;
    dst += (size_t)blockIdx.z * zdst;
    const int i0 = blockIdx.x * 32, j0 = blockIdx.y * 32;
    const int tid = threadIdx.x;
#pragma unroll
    for (int s = 0; s < 4; s++) {
        int ii = (tid >> 5) + s * 8, jj = tid & 31;
        t[ii][jj] = src[(size_t)(i0 + ii) * sStride + j0 + jj];
    }
    __syncthreads();
    if (tid < 128) {
        int jj = tid >> 2, grp = tid & 3;
        float v[8];
#pragma unroll
        for (int u = 0; u < 8; u++) v[u] = t[grp * 8 + u][jj];
        uint4 o0 = { f2tf32(v[0]), f2tf32(v[4]), f2tf32(v[1]), f2tf32(v[5]) };
        uint4 o1 = { f2tf32(v[2]), f2tf32(v[6]), f2tf32(v[3]), f2tf32(v[7]) };
        uint4* d = (uint4*)(dst + (size_t)(j0 + jj) * NI + i0 + grp * 8);
        d[0] = o0; d[1] = o1;
    }
}

// ---------------------------------------------------------------------------
// tf32 GEMM on packed operands: C[M x Ncols] = Ap[M x K] * Wp[Ncols x K]^T + bias
// BM=128, BN=128, BK=32; 256 thr / 8 warps; warp tile 32x64; 2-stage cp.async;
// zero cvt, all fragment loads LDS.64.  2 CTAs/SM.
// ---------------------------------------------------------------------------
#define LDAB  40
#define STGu  (128 * LDAB * 2)            // 10240 u32 per stage
#define GEMM_SMEM (STGu * 2 * 4)          // 81920 B

__global__ __launch_bounds__(256, 2) void gemm_tc(
    const uint32_t* __restrict__ A, const uint32_t* __restrict__ W,
    const float* __restrict__ bias, float* __restrict__ C,
    int Ncols, int K)
{
    extern __shared__ uint32_t sm[];
    const uint32_t sbase = smem_u32(sm);

    const int tid = threadIdx.x;
    const int lane = tid & 31;
    const int wid = tid >> 5;
    const int warp_m = wid & 3;
    const int warp_n = wid >> 2;
    const int g = lane >> 2;
    const int tg = lane & 3;
    const int bm = blockIdx.y * 128;
    const int bn = blockIdx.x * 128;

    const int a_r = tid >> 3;          // 0..31 (+32*s)
    const int a_c = (tid & 7) * 4;

    const uint32_t* Ab = A + (size_t)bm * K;
    const uint32_t* Wb = W + (size_t)bn * K;

    float acc[2][8][4];
#pragma unroll
    for (int mt = 0; mt < 2; mt++)
#pragma unroll
        for (int nt = 0; nt < 8; nt++)
#pragma unroll
            for (int j = 0; j < 4; j++) acc[mt][nt][j] = 0.f;

#define CPA_CHUNK(buf, k0) do { \
    const uint32_t so = sbase + (uint32_t)(buf) * (STGu * 4); \
    _Pragma("unroll") for (int s = 0; s < 4; s++) \
        CP_ASYNC16(so + ((a_r + 32 * s) * LDAB + a_c) * 4, \
                   Ab + (size_t)(a_r + 32 * s) * K + (k0) + a_c); \
    _Pragma("unroll") for (int s = 0; s < 4; s++) \
        CP_ASYNC16(so + (128 * LDAB + (a_r + 32 * s) * LDAB + a_c) * 4, \
                   Wb + (size_t)(a_r + 32 * s) * K + (k0) + a_c); \
    CP_COMMIT(); \
    } while (0)

#define MMA_CHUNK(buf) do { \
    const uint32_t* Ad = sm + (buf) * STGu; \
    const uint32_t* Bd = Ad + 128 * LDAB; \
    _Pragma("unroll") for (int ks = 0; ks < 4; ks++) { \
        uint32_t afr[2][4]; \
        _Pragma("unroll") for (int mt = 0; mt < 2; mt++) { \
            const int mr = warp_m * 32 + mt * 16; \
            uint2 x0 = *(const uint2*)&Ad[(mr + g)     * LDAB + ks * 8 + 2 * tg]; \
            uint2 x1 = *(const uint2*)&Ad[(mr + g + 8) * LDAB + ks * 8 + 2 * tg]; \
            afr[mt][0] = x0.x; afr[mt][1] = x1.x; afr[mt][2] = x0.y; afr[mt][3] = x1.y; } \
        _Pragma("unroll") for (int nt = 0; nt < 8; nt++) { \
            uint2 bb = *(const uint2*)&Bd[(warp_n * 64 + nt * 8 + g) * LDAB + ks * 8 + 2 * tg]; \
            mma16n8k8(acc[0][nt], afr[0], &bb.x); \
            mma16n8k8(acc[1][nt], afr[1], &bb.x); } \
    } } while (0)

    const int NCHUNK = K / 32;
    CPA_CHUNK(0, 0);

    for (int c = 0; c < NCHUNK; c++) {
        if (c + 1 < NCHUNK) {
            CPA_CHUNK((c + 1) & 1, (c + 1) * 32);
            CP_WAIT(1);
        } else {
            CP_WAIT(0);
        }
        __syncthreads();
        MMA_CHUNK(c & 1);
        __syncthreads();
    }

#pragma unroll
    for (int mt = 0; mt < 2; mt++) {
        const int row0 = bm + warp_m * 32 + mt * 16 + g;
#pragma unroll
        for (int nt = 0; nt < 8; nt++) {
            const int col = bn + warp_n * 64 + nt * 8 + 2 * tg;
            const float bx = __ldg(&bias[col]);
            const float by = __ldg(&bias[col + 1]);
            float2 v0 = { acc[mt][nt][0] + bx, acc[mt][nt][1] + by };
            float2 v1 = { acc[mt][nt][2] + bx, acc[mt][nt][3] + by };
            *(float2*)(C + (size_t)row0 * Ncols + col) = v0;
            *(float2*)(C + (size_t)(row0 + 8) * Ncols + col) = v1;
        }
    }
}

// ---------------------------------------------------------------------------
// Flash MQA, tf32 mma, packed K / V^T operands via cp.async.
// FQ=128, FKV=64; K double-buffered (prefetch during PV), V prefetch during S.
// Output written directly as packed tf32 for gemm2.
// ---------------------------------------------------------------------------
#define FQ    128
#define FKV   64
#define LDQ   136
#define LDK   136
#define LDVT  72
#define LDP   68
#define OFF_Q  0
#define OFF_K  (FQ * LDQ)                        // 17408
#define OFF_V  (OFF_K + 2 * FKV * LDK)           // 34816
#define OFF_P  (OFF_V + Dcfg * LDVT)             // 44032
#define FLASH_SMEM ((OFF_P + FQ * LDP) * 4)      // 210944 B

__global__ __launch_bounds__(256) void flash_p(
    const float* __restrict__ qkv, const uint32_t* __restrict__ kp,
    const uint32_t* __restrict__ vtp, uint32_t* __restrict__ outp)
{
    extern __shared__ uint32_t smf[];
    const uint32_t sbase = smem_u32(smf);
    uint32_t* Qs = smf + OFF_Q;
    uint32_t* Ps = smf + OFF_P;

    const int tid = threadIdx.x;
    const int lane = tid & 31;
    const int wid = tid >> 5;
    const int g = lane >> 2;
    const int tg = lane & 3;

    const int qb = (gridDim.x - 1) - blockIdx.x;   // heavy blocks first
    const int h = blockIdx.y;
    const int b = blockIdx.z;
    const int q0 = qb * FQ;

    const float* qbase = qkv + (size_t)b * Ncfg * QKVN + h * Dcfg;
    const uint32_t* kpb = kp + (size_t)b * Ncfg * Dcfg;
    const uint32_t* vtb = vtp + (size_t)b * Dcfg * Ncfg;

    const float S2 = 0.08838834764831845f * 1.4426950408889634f; // scale*log2e
    const float NEG = -1e30f;

    // Stage Q: fp32 -> tf32 + pack-permute into smem (once)
#pragma unroll
    for (int s = 0; s < 16; s++) {
        const int idx = s * 256 + tid;
        const int r = idx >> 5, c4 = (idx & 31) * 4;
        float4 v = *(const float4*)(qbase + (size_t)(q0 + r) * QKVN + c4);
        uint32_t* q = Qs + r * LDQ + (c4 & ~7) + ((c4 >> 2) & 1);
        q[0] = f2tf32(v.x); q[2] = f2tf32(v.y);
        q[4] = f2tf32(v.z); q[6] = f2tf32(v.w);
    }

#define STAGE_K(slot, k0) do { \
    _Pragma("unroll") for (int s = 0; s < 8; s++) { \
        const int idx = s * 256 + tid; \
        const int r = idx >> 5, c4 = (idx & 31) * 4; \
        CP_ASYNC16(sbase + (OFF_K + (slot) * (FKV * LDK) + r * LDK + c4) * 4, \
                   kpb + (size_t)((k0) + r) * Dcfg + c4); } \
    CP_COMMIT(); } while (0)

#define STAGE_V(k0) do { \
    _Pragma("unroll") for (int s = 0; s < 8; s++) { \
        const int idx = s * 256 + tid; \
        const int r = idx >> 4, c4 = (idx & 15) * 4; \
        CP_ASYNC16(sbase + (OFF_V + r * LDVT + c4) * 4, \
                   vtb + (size_t)r * Ncfg + (k0) + c4); } \
    CP_COMMIT(); } while (0)

    float ofr[16][4];
#pragma unroll
    for (int nt = 0; nt < 16; nt++)
#pragma unroll
        for (int j = 0; j < 4; j++) ofr[nt][j] = 0.f;
    float m0 = NEG, m1 = NEG, l0 = 0.f, l1 = 0.f;

    const int wrow = 16 * wid + g;
    const int row0 = q0 + wrow;
    const int row1 = row0 + 8;
    const int nkv = 2 * (qb + 1);

    STAGE_K(0, 0);

    for (int kb = 0; kb < nkv; kb++) {
        __syncthreads();                    // Vs/Ps free (prev PV done)
        STAGE_V(kb * FKV);
        CP_WAIT(1);                         // K[kb] landed (V outstanding)
        __syncthreads();                    // K visible to all warps

        const uint32_t* Kc = smf + OFF_K + (kb & 1) * (FKV * LDK);
        const uint32_t* Vc = smf + OFF_V;

        // S = Q K^T
        float sfr[8][4];
#pragma unroll
        for (int nt = 0; nt < 8; nt++)
#pragma unroll
            for (int j = 0; j < 4; j++) sfr[nt][j] = 0.f;

#pragma unroll
        for (int ks = 0; ks < 16; ks++) {
            uint2 qa = *(const uint2*)&Qs[(wrow)     * LDQ + ks * 8 + 2 * tg];
            uint2 qc = *(const uint2*)&Qs[(wrow + 8) * LDQ + ks * 8 + 2 * tg];
            uint32_t afr[4] = { qa.x, qc.x, qa.y, qc.y };
#pragma unroll
            for (int nt = 0; nt < 8; nt++) {
                uint2 kk = *(const uint2*)&Kc[(8 * nt + g) * LDK + ks * 8 + 2 * tg];
                mma16n8k8(sfr[nt], afr, &kk.x);
            }
        }

        // scale + causal mask
#pragma unroll
        for (int nt = 0; nt < 8; nt++)
#pragma unroll
            for (int j = 0; j < 4; j++) sfr[nt][j] *= S2;

        const int k0 = kb * FKV;
        if (kb >= nkv - 2) {
#pragma unroll
            for (int nt = 0; nt < 8; nt++) {
                const int c0 = k0 + 8 * nt + 2 * tg;
                if (c0     > row0) sfr[nt][0] = NEG;
                if (c0 + 1 > row0) sfr[nt][1] = NEG;
                if (c0     > row1) sfr[nt][2] = NEG;
                if (c0 + 1 > row1) sfr[nt][3] = NEG;
            }
        }

        // online softmax
        float mx0 = NEG, mx1 = NEG;
#pragma unroll
        for (int nt = 0; nt < 8; nt++) {
            mx0 = fmaxf(mx0, fmaxf(sfr[nt][0], sfr[nt][1]));
            mx1 = fmaxf(mx1, fmaxf(sfr[nt][2], sfr[nt][3]));
        }
        mx0 = fmaxf(mx0, __shfl_xor_sync(0xffffffff, mx0, 1));
        mx0 = fmaxf(mx0, __shfl_xor_sync(0xffffffff, mx0, 2));
        mx1 = fmaxf(mx1, __shfl_xor_sync(0xffffffff, mx1, 1));
        mx1 = fmaxf(mx1, __shfl_xor_sync(0xffffffff, mx1, 2));

        const float mn0 = fmaxf(m0, mx0);
        const float mn1 = fmaxf(m1, mx1);
        const float scl0 = ex2(m0 - mn0);
        const float scl1 = ex2(m1 - mn1);

        float sum0 = 0.f, sum1 = 0.f;
#pragma unroll
        for (int nt = 0; nt < 8; nt++) {
            sfr[nt][0] = ex2(sfr[nt][0] - mn0);
            sfr[nt][1] = ex2(sfr[nt][1] - mn0);
            sfr[nt][2] = ex2(sfr[nt][2] - mn1);
            sfr[nt][3] = ex2(sfr[nt][3] - mn1);
            sum0 += sfr[nt][0] + sfr[nt][1];
            sum1 += sfr[nt][2] + sfr[nt][3];
        }
        sum0 += __shfl_xor_sync(0xffffffff, sum0, 1);
        sum0 += __shfl_xor_sync(0xffffffff, sum0, 2);
        sum1 += __shfl_xor_sync(0xffffffff, sum1, 1);
        sum1 += __shfl_xor_sync(0xffffffff, sum1, 2);

        l0 = l0 * scl0 + sum0;  m0 = mn0;
        l1 = l1 * scl1 + sum1;  m1 = mn1;

        // prefetch next K tile (covers the PV phase)
        if (kb + 1 < nkv) STAGE_K((kb + 1) & 1, (kb + 1) * FKV);

        // store P (tf32, unpermuted)
#pragma unroll
        for (int nt = 0; nt < 8; nt++) {
            uint2 p0 = { f2tf32(sfr[nt][0]), f2tf32(sfr[nt][1]) };
            uint2 p1 = { f2tf32(sfr[nt][2]), f2tf32(sfr[nt][3]) };
            *(uint2*)(Ps + (wrow)     * LDP + 8 * nt + 2 * tg) = p0;
            *(uint2*)(Ps + (wrow + 8) * LDP + 8 * nt + 2 * tg) = p1;
        }

        // rescale O
#pragma unroll
        for (int nt = 0; nt < 16; nt++) {
            ofr[nt][0] *= scl0; ofr[nt][1] *= scl0;
            ofr[nt][2] *= scl1; ofr[nt][3] *= scl1;
        }

        if (kb + 1 < nkv) { CP_WAIT(1); } else { CP_WAIT(0); }   // V[kb] done
        __syncthreads();                    // V + P visible

        // O += P V
#pragma unroll
        for (int ks = 0; ks < 8; ks++) {
            uint32_t afr[4];
            afr[0] = Ps[(wrow)     * LDP + 8 * ks + tg];
            afr[1] = Ps[(wrow + 8) * LDP + 8 * ks + tg];
            afr[2] = Ps[(wrow)     * LDP + 8 * ks + tg + 4];
            afr[3] = Ps[(wrow + 8) * LDP + 8 * ks + tg + 4];
#pragma unroll
            for (int nt = 0; nt < 16; nt++) {
                uint2 vv = *(const uint2*)&Vc[(8 * nt + g) * LDVT + ks * 8 + 2 * tg];
                mma16n8k8(ofr[nt], afr, &vv.x);
            }
        }
    }

    // epilogue: write packed tf32 (position perm within 8-groups)
    const float rl0 = 1.f / l0;
    const float rl1 = 1.f / l1;
    const int p0 = ((2 * tg) & 3) * 2 + (tg >> 1);   // perm8(2tg)
    uint32_t* o0 = outp + (size_t)(b * Ncfg + row0) * Ecfg + h * Dcfg;
    uint32_t* o1 = outp + (size_t)(b * Ncfg + row1) * Ecfg + h * Dcfg;
#pragma unroll
    for (int nt = 0; nt < 16; nt++) {
        const int cb = 8 * nt;
        o0[cb + p0]     = f2tf32(ofr[nt][0] * rl0);
        o0[cb + p0 + 2] = f2tf32(ofr[nt][1] * rl0);
        o1[cb + p0]     = f2tf32(ofr[nt][2] * rl1);
        o1[cb + p0 + 2] = f2tf32(ofr[nt][3] * rl1);
    }
}

// ---------------------------------------------------------------------------
extern "C" void kernel_launch(void* const* d_in, const int* in_sizes, int n_in,
                              void* d_out, int out_size)
{
    const float* x     = (const float*)d_in[0];
    const float* w_qkv = (const float*)d_in[1];
    const float* b_qkv = (const float*)d_in[2];
    const float* w_fc  = (const float*)d_in[3];
    const float* b_fc  = (const float*)d_in[4];
    float* out = (float*)d_out;

    float* qkv_ptr;  uint32_t *xp, *wqkvp, *wfcp, *kpp, *vtpp, *attnp;
    cudaGetSymbolAddress((void**)&qkv_ptr, g_qkv);
    cudaGetSymbolAddress((void**)&xp, g_xp);
    cudaGetSymbolAddress((void**)&wqkvp, g_wqkvp);
    cudaGetSymbolAddress((void**)&wfcp, g_wfcp);
    cudaGetSymbolAddress((void**)&kpp, g_kp);
    cudaGetSymbolAddress((void**)&vtpp, g_vtp);
    cudaGetSymbolAddress((void**)&attnp, g_attnp);

    cudaFuncSetAttribute(gemm_tc, cudaFuncAttributeMaxDynamicSharedMemorySize, GEMM_SMEM);
    cudaFuncSetAttribute(flash_p, cudaFuncAttributeMaxDynamicSharedMemorySize, FLASH_SMEM);

    // 0) pack x; transpose+pack weights
    pack_tf32_flat<<<(Mrows * Ecfg / 8 + 255) / 256, 256>>>(x, xp, (size_t)Mrows * Ecfg / 8);
    transpose_pack<<<dim3(Ecfg / 32, QKVN / 32, 1), 256>>>(w_qkv, QKVN, 0, wqkvp, 0, Ecfg);
    transpose_pack<<<dim3(Ecfg / 32, Ecfg / 32, 1), 256>>>(w_fc, Ecfg, 0, wfcp, 0, Ecfg);

    // 1) qkv = x @ w_qkv + b_qkv
    gemm_tc<<<dim3(QKVN / 128, Mrows / 128), 256, GEMM_SMEM>>>(
        xp, wqkvp, b_qkv, qkv_ptr, QKVN, Ecfg);

    // 2) pack K and V^T from qkv
    pack_k_kernel<<<Mrows * 16 / 256, 256>>>(qkv_ptr, kpp);
    transpose_pack<<<dim3(Ncfg / 32, Dcfg / 32, Bcfg), 256>>>(
        qkv_ptr + Ecfg + Dcfg, QKVN, (size_t)Ncfg * QKVN, vtpp, (size_t)Dcfg * Ncfg, Ncfg);

    // 3) flash attention -> packed attn
    flash_p<<<dim3(Ncfg / FQ, Hcfg, Bcfg), 256, FLASH_SMEM>>>(
        qkv_ptr, kpp, vtpp, attnp);

    // 4) out = attn @ w_fc + b_fc
    gemm_tc<<<dim3(Ecfg / 128, Mrows / 128), 256, GEMM_SMEM>>>(
        attnp, wfcp, b_fc, out, Ecfg, Ecfg);
}

// round 6
// speedup vs baseline: 6.6534x; 1.0446x over previous
#include <cuda_runtime.h>
#include <cuda_bf16.h>
#include <cstdint>

// Problem constants
#define Ecfg   2048
#define Hcfg   16
#define Dcfg   128
#define Bcfg   4
#define Ncfg   2048
#define QKVN   (Ecfg + 2 * Dcfg)   // 2304
#define Mrows  (Bcfg * Ncfg)       // 8192
#define GK     2048                // K of both GEMMs (compile-time)

// Scratch (allocation-free rule: __device__ globals)
__device__ float    g_qkv[(size_t)Mrows * QKVN];     // qkv fp32 (Q read from here)
__device__ uint32_t g_xp[(size_t)Mrows * Ecfg];      // x packed tf32
__device__ uint32_t g_wqkvp[(size_t)QKVN * Ecfg];    // w_qkv^T packed
__device__ uint32_t g_wfcp[(size_t)Ecfg * Ecfg];     // w_fc^T packed
__device__ uint32_t g_kp[(size_t)Mrows * Dcfg];      // K packed [b*N][128]
__device__ uint32_t g_vtp[(size_t)Bcfg * Dcfg * Ncfg]; // V^T packed [b][128][N]
__device__ uint32_t g_attnp[(size_t)Mrows * Ecfg];   // attn out packed tf32

// ---------------------------------------------------------------------------
// helpers
// ---------------------------------------------------------------------------
__device__ __forceinline__ uint32_t f2tf32(float x) {
    uint32_t u;
    asm("cvt.rna.tf32.f32 %0, %1;" : "=r"(u) : "f"(x));
    return u;
}
__device__ __forceinline__ float ex2(float x) {
    float y;
    asm("ex2.approx.ftz.f32 %0, %1;" : "=f"(y) : "f"(x));
    return y;
}
__device__ __forceinline__ void mma16n8k8(float* d, const uint32_t* a, const uint32_t* b) {
    asm volatile(
        "mma.sync.aligned.m16n8k8.row.col.f32.tf32.tf32.f32 "
        "{%0,%1,%2,%3}, {%4,%5,%6,%7}, {%8,%9}, {%0,%1,%2,%3};\n"
        : "+f"(d[0]), "+f"(d[1]), "+f"(d[2]), "+f"(d[3])
        : "r"(a[0]), "r"(a[1]), "r"(a[2]), "r"(a[3]), "r"(b[0]), "r"(b[1]));
}
__device__ __forceinline__ uint32_t smem_u32(const void* p) {
    uint32_t a;
    asm("{ .reg .u64 t; cvta.to.shared.u64 t, %1; cvt.u32.u64 %0, t; }" : "=r"(a) : "l"(p));
    return a;
}
#define CP_ASYNC16(sa, gp) \
    asm volatile("cp.async.cg.shared.global [%0], [%1], 16;" :: "r"(sa), "l"(gp))
#define CP_COMMIT() asm volatile("cp.async.commit_group;" ::: "memory")
#define CP_WAIT(n)  asm volatile("cp.async.wait_group %0;" :: "n"(n) : "memory")

// ---------------------------------------------------------------------------
// prep kernel 1: elementwise fp32 -> packed tf32 (flat, groups of 8)
// ---------------------------------------------------------------------------
__global__ __launch_bounds__(256) void pack_tf32_flat(
    const float* __restrict__ src, uint32_t* __restrict__ dst, size_t n8)
{
    size_t t = (size_t)blockIdx.x * 256 + threadIdx.x;
    if (t >= n8) return;
    const float4* s = (const float4*)(src + t * 8);
    float4 a = s[0], b = s[1];
    uint4 o0 = { f2tf32(a.x), f2tf32(b.x), f2tf32(a.y), f2tf32(b.y) };
    uint4 o1 = { f2tf32(a.z), f2tf32(b.z), f2tf32(a.w), f2tf32(b.w) };
    uint4* d = (uint4*)(dst + t * 8);
    d[0] = o0; d[1] = o1;
}

// ---------------------------------------------------------------------------
// prep kernel 2: K slice of qkv -> packed [8192][128]
// ---------------------------------------------------------------------------
__global__ __launch_bounds__(256) void pack_k_kernel(
    const float* __restrict__ qkv, uint32_t* __restrict__ kp)
{
    int t = blockIdx.x * 256 + threadIdx.x;       // 8192*16
    int row = t >> 4, grp = t & 15;
    const float4* s = (const float4*)(qkv + (size_t)row * QKVN + Ecfg + grp * 8);
    float4 a = s[0], b = s[1];
    uint4 o0 = { f2tf32(a.x), f2tf32(b.x), f2tf32(a.y), f2tf32(b.y) };
    uint4 o1 = { f2tf32(a.z), f2tf32(b.z), f2tf32(a.w), f2tf32(b.w) };
    uint4* d = (uint4*)(kp + (size_t)row * Dcfg + grp * 8);
    d[0] = o0; d[1] = o1;
}

// ---------------------------------------------------------------------------
// prep kernel 3: transpose + pack:  dst[j][packed(i)] = src[i][j]
// ---------------------------------------------------------------------------
__global__ __launch_bounds__(256) void transpose_pack(
    const float* __restrict__ src, size_t sStride, size_t zsrc,
    uint32_t* __restrict__ dst, size_t zdst, int NI)
{
    __shared__ float t[32][33];
    src += (size_t)blockIdx.z * zsrc;
    dst += (size_t)blockIdx.z * zdst;
    const int i0 = blockIdx.x * 32, j0 = blockIdx.y * 32;
    const int tid = threadIdx.x;
#pragma unroll
    for (int s = 0; s < 4; s++) {
        int ii = (tid >> 5) + s * 8, jj = tid & 31;
        t[ii][jj] = src[(size_t)(i0 + ii) * sStride + j0 + jj];
    }
    __syncthreads();
    if (tid < 128) {
        int jj = tid >> 2, grp = tid & 3;
        float v[8];
#pragma unroll
        for (int u = 0; u < 8; u++) v[u] = t[grp * 8 + u][jj];
        uint4 o0 = { f2tf32(v[0]), f2tf32(v[4]), f2tf32(v[1]), f2tf32(v[5]) };
        uint4 o1 = { f2tf32(v[2]), f2tf32(v[6]), f2tf32(v[3]), f2tf32(v[7]) };
        uint4* d = (uint4*)(dst + (size_t)(j0 + jj) * NI + i0 + grp * 8);
        d[0] = o0; d[1] = o1;
    }
}

// ---------------------------------------------------------------------------
// tf32 GEMM on packed operands: C = Ap[M x 2048] * Wp[Ncols x 2048]^T + bias
// BM=128, BN=128, BK=32; 3-stage cp.async, ONE __syncthreads per chunk;
// XOR-swizzled smem (no pad): stage = 2 x 128 x 32 u32 = 32KB; 2 CTAs/SM.
// ---------------------------------------------------------------------------
#define NST   3
#define HSTG  4096                         // u32 per A (or B) half-stage
#define STGu  (2 * HSTG)                   // 8192 u32 per stage
#define GEMM_SMEM (NST * STGu * 4)         // 98304 B

__global__ __launch_bounds__(256, 2) void gemm_tc(
    const uint32_t* __restrict__ A, const uint32_t* __restrict__ W,
    const float* __restrict__ bias, float* __restrict__ C,
    int Ncols)
{
    extern __shared__ uint32_t sm[];
    const uint32_t sbase = smem_u32(sm);

    const int tid = threadIdx.x;
    const int lane = tid & 31;
    const int wid = tid >> 5;
    const int warp_m = wid & 3;
    const int warp_n = wid >> 2;
    const int g = lane >> 2;
    const int tg = lane & 3;
    const int bm = blockIdx.y * 128;
    const int bn = blockIdx.x * 128;

    const int a_r = tid >> 3;               // 0..31 (+32*s)
    const int a_c = (tid & 7) * 4;          // 0..28
    const int dstc = a_c ^ ((a_r & 3) << 3);  // swizzled dst col

    const uint32_t* asrc = A + (size_t)(bm + a_r) * GK + a_c;
    const uint32_t* bsrc = W + (size_t)(bn + a_r) * GK + a_c;

    float acc[2][8][4];
#pragma unroll
    for (int mt = 0; mt < 2; mt++)
#pragma unroll
        for (int nt = 0; nt < 8; nt++)
#pragma unroll
            for (int j = 0; j < 4; j++) acc[mt][nt][j] = 0.f;

#define CPA_CHUNK(buf, k0) do { \
    const uint32_t so = sbase + (uint32_t)(buf) * (STGu * 4); \
    _Pragma("unroll") for (int s = 0; s < 4; s++) \
        CP_ASYNC16(so + (((a_r + 32 * s) << 5) + dstc) * 4, \
                   asrc + (size_t)(32 * s) * GK + (k0)); \
    _Pragma("unroll") for (int s = 0; s < 4; s++) \
        CP_ASYNC16(so + ((HSTG + ((a_r + 32 * s) << 5) + dstc) * 4), \
                   bsrc + (size_t)(32 * s) * GK + (k0)); \
    CP_COMMIT(); \
    } while (0)

#define MMA_CHUNK(buf) do { \
    const uint32_t* Ad = sm + (buf) * STGu; \
    const uint32_t* Bd = Ad + HSTG; \
    const int csw = (g & 3) << 3; \
    _Pragma("unroll") for (int ks = 0; ks < 4; ks++) { \
        const int col = (8 * ks + 2 * tg) ^ csw; \
        uint32_t afr[2][4]; \
        { uint2 x0 = *(const uint2*)&Ad[((warp_m * 32 + g)      << 5) + col]; \
          uint2 x1 = *(const uint2*)&Ad[((warp_m * 32 + 16 + g) << 5) + col]; \
          afr[0][0] = x0.x; afr[0][1] = x1.x; afr[0][2] = x0.y; afr[0][3] = x1.y; } \
        { uint2 y0 = *(const uint2*)&Ad[((warp_m * 32 + 8 + g)  << 5) + col]; \
          uint2 y1 = *(const uint2*)&Ad[((warp_m * 32 + 24 + g) << 5) + col]; \
          afr[1][0] = y0.x; afr[1][1] = y1.x; afr[1][2] = y0.y; afr[1][3] = y1.y; } \
        _Pragma("unroll") for (int nt = 0; nt < 8; nt++) { \
            uint2 bb = *(const uint2*)&Bd[((warp_n * 64 + nt * 8 + g) << 5) + col]; \
            mma16n8k8(acc[0][nt], afr[0], &bb.x); \
            mma16n8k8(acc[1][nt], afr[1], &bb.x); } \
    } } while (0)

    const int NCHUNK = GK / 32;            // 64
    CPA_CHUNK(0, 0);
    CPA_CHUNK(1, 32);

    for (int c = 0; c < NCHUNK; c++) {
        if (c + 1 < NCHUNK) { CP_WAIT(1); } else { CP_WAIT(0); }
        __syncthreads();
        const int buf = c % NST;
        MMA_CHUNK(buf);
        if (c + 2 < NCHUNK) {
            CPA_CHUNK((c + 2) % NST, (c + 2) * 32);
        }
    }

    // Epilogue. Note acc[0] rows: +0/+16 group... mapping below matches MMA_CHUNK:
    // afr[0] covers rows (warp_m*32 + g, +16) -> m16 tile rows {g, g+8} of tiles {0,16}
#pragma unroll
    for (int mt = 0; mt < 2; mt++) {
        const int row0 = bm + warp_m * 32 + mt * 8 + g;       // mt0: rows g,(+16); mt1: rows 8+g,(+16)
#pragma unroll
        for (int nt = 0; nt < 8; nt++) {
            const int col = bn + warp_n * 64 + nt * 8 + 2 * tg;
            const float bx = __ldg(&bias[col]);
            const float by = __ldg(&bias[col + 1]);
            float2 v0 = { acc[mt][nt][0] + bx, acc[mt][nt][1] + by };
            float2 v1 = { acc[mt][nt][2] + bx, acc[mt][nt][3] + by };
            *(float2*)(C + (size_t)row0 * Ncols + col) = v0;
            *(float2*)(C + (size_t)(row0 + 16) * Ncols + col) = v1;
        }
    }
}

// ---------------------------------------------------------------------------
// Flash MQA, tf32 mma, packed K / V^T operands via cp.async. (round-5 kernel)
// ---------------------------------------------------------------------------
#define FQ    128
#define FKV   64
#define LDQ   136
#define LDK   136
#define LDVT  72
#define LDP   68
#define OFF_Q  0
#define OFF_K  (FQ * LDQ)                        // 17408
#define OFF_V  (OFF_K + 2 * FKV * LDK)           // 34816
#define OFF_P  (OFF_V + Dcfg * LDVT)             // 44032
#define FLASH_SMEM ((OFF_P + FQ * LDP) * 4)      // 210944 B

__global__ __launch_bounds__(256) void flash_p(
    const float* __restrict__ qkv, const uint32_t* __restrict__ kp,
    const uint32_t* __restrict__ vtp, uint32_t* __restrict__ outp)
{
    extern __shared__ uint32_t smf[];
    const uint32_t sbase = smem_u32(smf);
    uint32_t* Qs = smf + OFF_Q;
    uint32_t* Ps = smf + OFF_P;

    const int tid = threadIdx.x;
    const int lane = tid & 31;
    const int wid = tid >> 5;
    const int g = lane >> 2;
    const int tg = lane & 3;

    const int qb = (gridDim.x - 1) - blockIdx.x;   // heavy blocks first
    const int h = blockIdx.y;
    const int b = blockIdx.z;
    const int q0 = qb * FQ;

    const float* qbase = qkv + (size_t)b * Ncfg * QKVN + h * Dcfg;
    const uint32_t* kpb = kp + (size_t)b * Ncfg * Dcfg;
    const uint32_t* vtb = vtp + (size_t)b * Dcfg * Ncfg;

    const float S2 = 0.08838834764831845f * 1.4426950408889634f; // scale*log2e
    const float NEG = -1e30f;

    // Stage Q: fp32 -> tf32 + pack-permute into smem (once)
#pragma unroll
    for (int s = 0; s < 16; s++) {
        const int idx = s * 256 + tid;
        const int r = idx >> 5, c4 = (idx & 31) * 4;
        float4 v = *(const float4*)(qbase + (size_t)(q0 + r) * QKVN + c4);
        uint32_t* q = Qs + r * LDQ + (c4 & ~7) + ((c4 >> 2) & 1);
        q[0] = f2tf32(v.x); q[2] = f2tf32(v.y);
        q[4] = f2tf32(v.z); q[6] = f2tf32(v.w);
    }

#define STAGE_K(slot, k0) do { \
    _Pragma("unroll") for (int s = 0; s < 8; s++) { \
        const int idx = s * 256 + tid; \
        const int r = idx >> 5, c4 = (idx & 31) * 4; \
        CP_ASYNC16(sbase + (OFF_K + (slot) * (FKV * LDK) + r * LDK + c4) * 4, \
                   kpb + (size_t)((k0) + r) * Dcfg + c4); } \
    CP_COMMIT(); } while (0)

#define STAGE_V(k0) do { \
    _Pragma("unroll") for (int s = 0; s < 8; s++) { \
        const int idx = s * 256 + tid; \
        const int r = idx >> 4, c4 = (idx & 15) * 4; \
        CP_ASYNC16(sbase + (OFF_V + r * LDVT + c4) * 4, \
                   vtb + (size_t)r * Ncfg + (k0) + c4); } \
    CP_COMMIT(); } while (0)

    float ofr[16][4];
#pragma unroll
    for (int nt = 0; nt < 16; nt++)
#pragma unroll
        for (int j = 0; j < 4; j++) ofr[nt][j] = 0.f;
    float m0 = NEG, m1 = NEG, l0 = 0.f, l1 = 0.f;

    const int wrow = 16 * wid + g;
    const int row0 = q0 + wrow;
    const int row1 = row0 + 8;
    const int nkv = 2 * (qb + 1);

    STAGE_K(0, 0);

    for (int kb = 0; kb < nkv; kb++) {
        __syncthreads();                    // Vs/Ps free (prev PV done)
        STAGE_V(kb * FKV);
        CP_WAIT(1);                         // K[kb] landed (V outstanding)
        __syncthreads();                    // K visible to all warps

        const uint32_t* Kc = smf + OFF_K + (kb & 1) * (FKV * LDK);
        const uint32_t* Vc = smf + OFF_V;

        // S = Q K^T
        float sfr[8][4];
#pragma unroll
        for (int nt = 0; nt < 8; nt++)
#pragma unroll
            for (int j = 0; j < 4; j++) sfr[nt][j] = 0.f;

#pragma unroll
        for (int ks = 0; ks < 16; ks++) {
            uint2 qa = *(const uint2*)&Qs[(wrow)     * LDQ + ks * 8 + 2 * tg];
            uint2 qc = *(const uint2*)&Qs[(wrow + 8) * LDQ + ks * 8 + 2 * tg];
            uint32_t afr[4] = { qa.x, qc.x, qa.y, qc.y };
#pragma unroll
            for (int nt = 0; nt < 8; nt++) {
                uint2 kk = *(const uint2*)&Kc[(8 * nt + g) * LDK + ks * 8 + 2 * tg];
                mma16n8k8(sfr[nt], afr, &kk.x);
            }
        }

        // scale + causal mask
#pragma unroll
        for (int nt = 0; nt < 8; nt++)
#pragma unroll
            for (int j = 0; j < 4; j++) sfr[nt][j] *= S2;

        const int k0 = kb * FKV;
        if (kb >= nkv - 2) {
#pragma unroll
            for (int nt = 0; nt < 8; nt++) {
                const int c0 = k0 + 8 * nt + 2 * tg;
                if (c0     > row0) sfr[nt][0] = NEG;
                if (c0 + 1 > row0) sfr[nt][1] = NEG;
                if (c0     > row1) sfr[nt][2] = NEG;
                if (c0 + 1 > row1) sfr[nt][3] = NEG;
            }
        }

        // online softmax
        float mx0 = NEG, mx1 = NEG;
#pragma unroll
        for (int nt = 0; nt < 8; nt++) {
            mx0 = fmaxf(mx0, fmaxf(sfr[nt][0], sfr[nt][1]));
            mx1 = fmaxf(mx1, fmaxf(sfr[nt][2], sfr[nt][3]));
        }
        mx0 = fmaxf(mx0, __shfl_xor_sync(0xffffffff, mx0, 1));
        mx0 = fmaxf(mx0, __shfl_xor_sync(0xffffffff, mx0, 2));
        mx1 = fmaxf(mx1, __shfl_xor_sync(0xffffffff, mx1, 1));
        mx1 = fmaxf(mx1, __shfl_xor_sync(0xffffffff, mx1, 2));

        const float mn0 = fmaxf(m0, mx0);
        const float mn1 = fmaxf(m1, mx1);
        const float scl0 = ex2(m0 - mn0);
        const float scl1 = ex2(m1 - mn1);

        float sum0 = 0.f, sum1 = 0.f;
#pragma unroll
        for (int nt = 0; nt < 8; nt++) {
            sfr[nt][0] = ex2(sfr[nt][0] - mn0);
            sfr[nt][1] = ex2(sfr[nt][1] - mn0);
            sfr[nt][2] = ex2(sfr[nt][2] - mn1);
            sfr[nt][3] = ex2(sfr[nt][3] - mn1);
            sum0 += sfr[nt][0] + sfr[nt][1];
            sum1 += sfr[nt][2] + sfr[nt][3];
        }
        sum0 += __shfl_xor_sync(0xffffffff, sum0, 1);
        sum0 += __shfl_xor_sync(0xffffffff, sum0, 2);
        sum1 += __shfl_xor_sync(0xffffffff, sum1, 1);
        sum1 += __shfl_xor_sync(0xffffffff, sum1, 2);

        l0 = l0 * scl0 + sum0;  m0 = mn0;
        l1 = l1 * scl1 + sum1;  m1 = mn1;

        // prefetch next K tile (covers the PV phase)
        if (kb + 1 < nkv) STAGE_K((kb + 1) & 1, (kb + 1) * FKV);

        // store P (tf32, unpermuted)
#pragma unroll
        for (int nt = 0; nt < 8; nt++) {
            uint2 p0 = { f2tf32(sfr[nt][0]), f2tf32(sfr[nt][1]) };
            uint2 p1 = { f2tf32(sfr[nt][2]), f2tf32(sfr[nt][3]) };
            *(uint2*)(Ps + (wrow)     * LDP + 8 * nt + 2 * tg) = p0;
            *(uint2*)(Ps + (wrow + 8) * LDP + 8 * nt + 2 * tg) = p1;
        }

        // rescale O
#pragma unroll
        for (int nt = 0; nt < 16; nt++) {
            ofr[nt][0] *= scl0; ofr[nt][1] *= scl0;
            ofr[nt][2] *= scl1; ofr[nt][3] *= scl1;
        }

        if (kb + 1 < nkv) { CP_WAIT(1); } else { CP_WAIT(0); }   // V[kb] done
        __syncthreads();                    // V + P visible

        // O += P V
#pragma unroll
        for (int ks = 0; ks < 8; ks++) {
            uint32_t afr[4];
            afr[0] = Ps[(wrow)     * LDP + 8 * ks + tg];
            afr[1] = Ps[(wrow + 8) * LDP + 8 * ks + tg];
            afr[2] = Ps[(wrow)     * LDP + 8 * ks + tg + 4];
            afr[3] = Ps[(wrow + 8) * LDP + 8 * ks + tg + 4];
#pragma unroll
            for (int nt = 0; nt < 16; nt++) {
                uint2 vv = *(const uint2*)&Vc[(8 * nt + g) * LDVT + ks * 8 + 2 * tg];
                mma16n8k8(ofr[nt], afr, &vv.x);
            }
        }
    }

    // epilogue: write packed tf32 (position perm within 8-groups)
    const float rl0 = 1.f / l0;
    const float rl1 = 1.f / l1;
    const int p0 = ((2 * tg) & 3) * 2 + (tg >> 1);   // perm8(2tg)
    uint32_t* o0 = outp + (size_t)(b * Ncfg + row0) * Ecfg + h * Dcfg;
    uint32_t* o1 = outp + (size_t)(b * Ncfg + row1) * Ecfg + h * Dcfg;
#pragma unroll
    for (int nt = 0; nt < 16; nt++) {
        const int cb = 8 * nt;
        o0[cb + p0]     = f2tf32(ofr[nt][0] * rl0);
        o0[cb + p0 + 2] = f2tf32(ofr[nt][1] * rl0);
        o1[cb + p0]     = f2tf32(ofr[nt][2] * rl1);
        o1[cb + p0 + 2] = f2tf32(ofr[nt][3] * rl1);
    }
}

// ---------------------------------------------------------------------------
extern "C" void kernel_launch(void* const* d_in, const int* in_sizes, int n_in,
                              void* d_out, int out_size)
{
    const float* x     = (const float*)d_in[0];
    const float* w_qkv = (const float*)d_in[1];
    const float* b_qkv = (const float*)d_in[2];
    const float* w_fc  = (const float*)d_in[3];
    const float* b_fc  = (const float*)d_in[4];
    float* out = (float*)d_out;

    float* qkv_ptr;  uint32_t *xp, *wqkvp, *wfcp, *kpp, *vtpp, *attnp;
    cudaGetSymbolAddress((void**)&qkv_ptr, g_qkv);
    cudaGetSymbolAddress((void**)&xp, g_xp);
    cudaGetSymbolAddress((void**)&wqkvp, g_wqkvp);
    cudaGetSymbolAddress((void**)&wfcp, g_wfcp);
    cudaGetSymbolAddress((void**)&kpp, g_kp);
    cudaGetSymbolAddress((void**)&vtpp, g_vtp);
    cudaGetSymbolAddress((void**)&attnp, g_attnp);

    cudaFuncSetAttribute(gemm_tc, cudaFuncAttributeMaxDynamicSharedMemorySize, GEMM_SMEM);
    cudaFuncSetAttribute(flash_p, cudaFuncAttributeMaxDynamicSharedMemorySize, FLASH_SMEM);

    // 0) pack x; transpose+pack weights
    pack_tf32_flat<<<(Mrows * Ecfg / 8 + 255) / 256, 256>>>(x, xp, (size_t)Mrows * Ecfg / 8);
    transpose_pack<<<dim3(Ecfg / 32, QKVN / 32, 1), 256>>>(w_qkv, QKVN, 0, wqkvp, 0, Ecfg);
    transpose_pack<<<dim3(Ecfg / 32, Ecfg / 32, 1), 256>>>(w_fc, Ecfg, 0, wfcp, 0, Ecfg);

    // 1) qkv = x @ w_qkv + b_qkv
    gemm_tc<<<dim3(QKVN / 128, Mrows / 128), 256, GEMM_SMEM>>>(
        xp, wqkvp, b_qkv, qkv_ptr, QKVN);

    // 2) pack K and V^T from qkv
    pack_k_kernel<<<Mrows * 16 / 256, 256>>>(qkv_ptr, kpp);
    transpose_pack<<<dim3(Ncfg / 32, Dcfg / 32, Bcfg), 256>>>(
        qkv_ptr + Ecfg + Dcfg, QKVN, (size_t)Ncfg * QKVN, vtpp, (size_t)Dcfg * Ncfg, Ncfg);

    // 3) flash attention -> packed attn
    flash_p<<<dim3(Ncfg / FQ, Hcfg, Bcfg), 256, FLASH_SMEM>>>(
        qkv_ptr, kpp, vtpp, attnp);

    // 4) out = attn @ w_fc + b_fc
    gemm_tc<<<dim3(Ecfg / 128, Mrows / 128), 256, GEMM_SMEM>>>(
        attnp, wfcp, b_fc, out, Ecfg);
}

// round 7
// speedup vs baseline: 11.6328x; 1.7484x over previous
#include <cuda_runtime.h>
#include <cuda_fp16.h>
#include <cstdint>

// Problem constants
#define Ecfg   2048
#define Hcfg   16
#define Dcfg   128
#define Bcfg   4
#define Ncfg   2048
#define QKVN   (Ecfg + 2 * Dcfg)   // 2304
#define Mrows  (Bcfg * Ncfg)       // 8192
#define GK     2048                // K of both GEMMs

// Scratch (allocation-free rule: __device__ globals) — all packed fp16 (u32 = half2)
__device__ float    g_qkv[(size_t)Mrows * QKVN];        // qkv fp32 (Q read from here)
__device__ uint32_t g_xp[(size_t)Mrows * Ecfg / 2];     // x fp16 perm-packed
__device__ uint32_t g_wqkvp[(size_t)QKVN * Ecfg / 2];   // w_qkv^T fp16 packed
__device__ uint32_t g_wfcp[(size_t)Ecfg * Ecfg / 2];    // w_fc^T fp16 packed
__device__ uint32_t g_kp[(size_t)Mrows * Dcfg / 2];     // K fp16 packed [b*N][64 u32]
__device__ uint32_t g_vtp[(size_t)Bcfg * Dcfg * Ncfg / 2]; // V^T fp16 packed [b][128][1024 u32]
__device__ uint32_t g_attnp[(size_t)Mrows * Ecfg / 2];  // attn fp16 packed

// ---------------------------------------------------------------------------
// helpers
// ---------------------------------------------------------------------------
__device__ __forceinline__ uint32_t h2(float lo, float hi) {
    __half2 h = __floats2half2_rn(lo, hi);
    return *(uint32_t*)&h;
}
__device__ __forceinline__ float ex2(float x) {
    float y;
    asm("ex2.approx.ftz.f32 %0, %1;" : "=f"(y) : "f"(x));
    return y;
}
__device__ __forceinline__ void mma_h(float* d, const uint32_t* a, const uint32_t* b) {
    asm volatile(
        "mma.sync.aligned.m16n8k16.row.col.f32.f16.f16.f32 "
        "{%0,%1,%2,%3}, {%4,%5,%6,%7}, {%8,%9}, {%0,%1,%2,%3};\n"
        : "+f"(d[0]), "+f"(d[1]), "+f"(d[2]), "+f"(d[3])
        : "r"(a[0]), "r"(a[1]), "r"(a[2]), "r"(a[3]), "r"(b[0]), "r"(b[1]));
}
__device__ __forceinline__ uint32_t smem_u32(const void* p) {
    uint32_t a;
    asm("{ .reg .u64 t; cvta.to.shared.u64 t, %1; cvt.u32.u64 %0, t; }" : "=r"(a) : "l"(p));
    return a;
}
#define CP_ASYNC16(sa, gp) \
    asm volatile("cp.async.cg.shared.global [%0], [%1], 16;" :: "r"(sa), "l"(gp))
#define CP_COMMIT() asm volatile("cp.async.commit_group;" ::: "memory")
#define CP_WAIT(n)  asm volatile("cp.async.wait_group %0;" :: "n"(n) : "memory")

// perm16 within every 16-k group: pair j (k=2j,2j+1) -> u32 slot 2*(j&3) + (j>>2)
// so the m16n8k16 fragment halves (2tg,2tg+1) & (8+2tg,8+2tg+1) sit in u32
// slots 2tg, 2tg+1  => one LDS.64 per fragment row.

// ---------------------------------------------------------------------------
// prep 1: flat fp32 -> packed fp16 (16 floats -> 8 u32 per thread)
// ---------------------------------------------------------------------------
__global__ __launch_bounds__(256) void pack_f16_flat(
    const float* __restrict__ src, uint32_t* __restrict__ dst, size_t n16)
{
    size_t t = (size_t)blockIdx.x * 256 + threadIdx.x;
    if (t >= n16) return;
    const float4* s = (const float4*)(src + t * 16);
    float4 a = s[0], b = s[1], c = s[2], d = s[3];
    uint4 o0 = { h2(a.x, a.y), h2(c.x, c.y), h2(a.z, a.w), h2(c.z, c.w) };
    uint4 o1 = { h2(b.x, b.y), h2(d.x, d.y), h2(b.z, b.w), h2(d.z, d.w) };
    uint4* o = (uint4*)(dst + t * 8);
    o[0] = o0; o[1] = o1;
}

// ---------------------------------------------------------------------------
// prep 2: K slice of qkv -> packed fp16 [8192][64 u32]
// ---------------------------------------------------------------------------
__global__ __launch_bounds__(256) void pack_k_kernel(
    const float* __restrict__ qkv, uint32_t* __restrict__ kp)
{
    int t = blockIdx.x * 256 + threadIdx.x;       // 8192*8
    int row = t >> 3, grp = t & 7;
    const float4* s = (const float4*)(qkv + (size_t)row * QKVN + Ecfg + grp * 16);
    float4 a = s[0], b = s[1], c = s[2], d = s[3];
    uint4 o0 = { h2(a.x, a.y), h2(c.x, c.y), h2(a.z, a.w), h2(c.z, c.w) };
    uint4 o1 = { h2(b.x, b.y), h2(d.x, d.y), h2(b.z, b.w), h2(d.z, d.w) };
    uint4* o = (uint4*)(kp + (size_t)row * (Dcfg / 2) + grp * 8);
    o[0] = o0; o[1] = o1;
}

// ---------------------------------------------------------------------------
// prep 3: transpose + pack fp16: dst[j][perm(i)] = src[i][j]
// grid (NI/32, NJ/32, nz); NIu = NI/2 (u32 row stride of dst)
// ---------------------------------------------------------------------------
__global__ __launch_bounds__(256) void transpose_pack(
    const float* __restrict__ src, size_t sStride, size_t zsrc,
    uint32_t* __restrict__ dst, size_t zdst, int NIu)
{
    __shared__ float t[32][33];
    src += (size_t)blockIdx.z * zsrc;
    dst += (size_t)blockIdx.z * zdst;
    const int i0 = blockIdx.x * 32, j0 = blockIdx.y * 32;
    const int tid = threadIdx.x;
#pragma unroll
    for (int s = 0; s < 4; s++) {
        int ii = (tid >> 5) + s * 8, jj = tid & 31;
        t[ii][jj] = src[(size_t)(i0 + ii) * sStride + j0 + jj];
    }
    __syncthreads();
    if (tid < 64) {
        int jj = tid >> 1, grp = tid & 1;
        float v[16];
#pragma unroll
        for (int u = 0; u < 16; u++) v[u] = t[grp * 16 + u][jj];
        uint4 o0 = { h2(v[0], v[1]), h2(v[8], v[9]), h2(v[2], v[3]), h2(v[10], v[11]) };
        uint4 o1 = { h2(v[4], v[5]), h2(v[12], v[13]), h2(v[6], v[7]), h2(v[14], v[15]) };
        uint4* o = (uint4*)(dst + (size_t)(j0 + jj) * NIu + i0 / 2 + grp * 8);
        o[0] = o0; o[1] = o1;
    }
}

// ---------------------------------------------------------------------------
// fp16 GEMM: C = Ap[M x 2048] * Wp[Ncols x 2048]^T + bias  (fp32 out)
// BM=128, BN=128, BK=32; 3-stage cp.async, one barrier per chunk.
// smem rows padded to 24 u32 (96B; 12 bank-pairs -> conflict-free LDS.64).
// ---------------------------------------------------------------------------
#define LDGh  24                            // u32 per smem row
#define HSTG  (128 * LDGh)                  // 3072 u32 per A (or B) half-stage
#define STGu  (2 * HSTG)                    // 6144 u32 per stage
#define NST   3
#define GEMM_SMEM (NST * STGu * 4)          // 73728 B

__global__ __launch_bounds__(256, 2) void gemm_tc(
    const uint32_t* __restrict__ A, const uint32_t* __restrict__ W,
    const float* __restrict__ bias, float* __restrict__ C,
    int Ncols)
{
    extern __shared__ uint32_t sm[];
    const uint32_t sbase = smem_u32(sm);

    const int tid = threadIdx.x;
    const int lane = tid & 31;
    const int wid = tid >> 5;
    const int warp_m = wid & 3;
    const int warp_n = wid >> 2;
    const int g = lane >> 2;
    const int tg = lane & 3;
    const int bm = blockIdx.y * 128;
    const int bn = blockIdx.x * 128;

    // staging: 512 16B-chunks per half-stage; 2 per thread per operand
    const int c_r = tid >> 2;               // 0..63 (+64)
    const int c_c = (tid & 3) * 4;          // u32 within row

    const uint32_t* asrc = A + (size_t)(bm + c_r) * (GK / 2) + c_c;
    const uint32_t* bsrc = W + (size_t)(bn + c_r) * (GK / 2) + c_c;

    float acc[2][8][4];
#pragma unroll
    for (int mt = 0; mt < 2; mt++)
#pragma unroll
        for (int nt = 0; nt < 8; nt++)
#pragma unroll
            for (int j = 0; j < 4; j++) acc[mt][nt][j] = 0.f;

#define CPA_CHUNK(buf, k0) do { \
    const uint32_t so = sbase + (uint32_t)(buf) * (STGu * 4); \
    _Pragma("unroll") for (int s = 0; s < 2; s++) \
        CP_ASYNC16(so + (((c_r + 64 * s) * LDGh) + c_c) * 4, \
                   asrc + (size_t)(64 * s) * (GK / 2) + ((k0) >> 1)); \
    _Pragma("unroll") for (int s = 0; s < 2; s++) \
        CP_ASYNC16(so + ((HSTG + (c_r + 64 * s) * LDGh + c_c) * 4), \
                   bsrc + (size_t)(64 * s) * (GK / 2) + ((k0) >> 1)); \
    CP_COMMIT(); \
    } while (0)

#define MMA_CHUNK(buf) do { \
    const uint32_t* Ad = sm + (buf) * STGu; \
    const uint32_t* Bd = Ad + HSTG; \
    _Pragma("unroll") for (int ks = 0; ks < 2; ks++) { \
        const int col = ks * 8 + 2 * tg; \
        uint32_t afr[2][4]; \
        _Pragma("unroll") for (int mt = 0; mt < 2; mt++) { \
            const int mr = warp_m * 32 + mt * 16; \
            uint2 x0 = *(const uint2*)&Ad[(mr + g)     * LDGh + col]; \
            uint2 x1 = *(const uint2*)&Ad[(mr + g + 8) * LDGh + col]; \
            afr[mt][0] = x0.x; afr[mt][1] = x1.x; afr[mt][2] = x0.y; afr[mt][3] = x1.y; } \
        _Pragma("unroll") for (int nt = 0; nt < 8; nt++) { \
            uint2 bb = *(const uint2*)&Bd[(warp_n * 64 + nt * 8 + g) * LDGh + col]; \
            mma_h(acc[0][nt], afr[0], &bb.x); \
            mma_h(acc[1][nt], afr[1], &bb.x); } \
    } } while (0)

    const int NCHUNK = GK / 32;             // 64
    CPA_CHUNK(0, 0);
    CPA_CHUNK(1, 32);

    for (int c = 0; c < NCHUNK; c++) {
        if (c + 1 < NCHUNK) { CP_WAIT(1); } else { CP_WAIT(0); }
        __syncthreads();
        MMA_CHUNK(c % NST);
        if (c + 2 < NCHUNK) CPA_CHUNK((c + 2) % NST, (c + 2) * 32);
    }

#pragma unroll
    for (int mt = 0; mt < 2; mt++) {
        const int row0 = bm + warp_m * 32 + mt * 16 + g;
#pragma unroll
        for (int nt = 0; nt < 8; nt++) {
            const int col = bn + warp_n * 64 + nt * 8 + 2 * tg;
            const float bx = __ldg(&bias[col]);
            const float by = __ldg(&bias[col + 1]);
            float2 v0 = { acc[mt][nt][0] + bx, acc[mt][nt][1] + by };
            float2 v1 = { acc[mt][nt][2] + bx, acc[mt][nt][3] + by };
            *(float2*)(C + (size_t)row0 * Ncols + col) = v0;
            *(float2*)(C + (size_t)(row0 + 8) * Ncols + col) = v1;
        }
    }
}

// ---------------------------------------------------------------------------
// Flash MQA, fp16 mma.  FQ=128, FKV=64; K double-buffered; V prefetch
// overlaps S-phase; output written packed fp16 for gemm2.
// All smem rows stride ≡ 12 bank-pairs mod 16 -> conflict-free LDS.64.
// ---------------------------------------------------------------------------
#define FQ     128
#define FKV    64
#define LDQ32  88        // 176 halves
#define LDK32  88
#define LDV32  56        // 112 halves
#define LDP32  56
#define OFF_Q  0
#define OFF_K  (FQ * LDQ32)                      // 11264
#define OFF_V  (OFF_K + 2 * FKV * LDK32)         // 22528
#define OFF_P  (OFF_V + Dcfg * LDV32)            // 29696
#define FLASH_SMEM ((OFF_P + FQ * LDP32) * 4)    // 147456 B

__global__ __launch_bounds__(256) void flash_h(
    const float* __restrict__ qkv, const uint32_t* __restrict__ kp,
    const uint32_t* __restrict__ vtp, uint32_t* __restrict__ outp)
{
    extern __shared__ uint32_t smf[];
    const uint32_t sbase = smem_u32(smf);
    uint32_t* Qs = smf + OFF_Q;
    uint32_t* Ps = smf + OFF_P;

    const int tid = threadIdx.x;
    const int lane = tid & 31;
    const int wid = tid >> 5;
    const int g = lane >> 2;
    const int tg = lane & 3;

    const int qb = (gridDim.x - 1) - blockIdx.x;   // heavy blocks first
    const int h = blockIdx.y;
    const int b = blockIdx.z;
    const int q0 = qb * FQ;

    const float* qbase = qkv + (size_t)b * Ncfg * QKVN + h * Dcfg;
    const uint32_t* kpb = kp + (size_t)b * Ncfg * (Dcfg / 2);
    const uint32_t* vtb = vtp + (size_t)b * Dcfg * (Ncfg / 2);

    const float S2 = 0.08838834764831845f * 1.4426950408889634f; // scale*log2e
    const float NEG = -1e30f;

    // Stage Q: fp32 -> fp16 perm-packed (once). 128 rows x 64 u32.
#pragma unroll
    for (int s = 0; s < 16; s++) {
        const int idx = s * 256 + tid;
        const int r = idx >> 5, c4 = (idx & 31) * 4;      // c4: float col, mult of 4
        float4 v = *(const float4*)(qbase + (size_t)(q0 + r) * QKVN + c4);
        const int j = c4 >> 1;                            // even pair index
        const int slot = 2 * (j & 3) + ((j >> 2) & 1);
        uint32_t* q = Qs + r * LDQ32 + (c4 >> 4) * 8;
        q[slot]     = h2(v.x, v.y);
        q[slot + 2] = h2(v.z, v.w);
    }

#define STAGE_K(slot_, k0) do { \
    _Pragma("unroll") for (int s = 0; s < 4; s++) { \
        const int idx = s * 256 + tid; \
        const int r = idx >> 4, c = (idx & 15) * 4; \
        CP_ASYNC16(sbase + (OFF_K + (slot_) * (FKV * LDK32) + r * LDK32 + c) * 4, \
                   kpb + (size_t)((k0) + r) * (Dcfg / 2) + c); } \
    CP_COMMIT(); } while (0)

#define STAGE_V(k0) do { \
    _Pragma("unroll") for (int s = 0; s < 4; s++) { \
        const int idx = s * 256 + tid; \
        const int r = idx >> 3, c = (idx & 7) * 4; \
        CP_ASYNC16(sbase + (OFF_V + r * LDV32 + c) * 4, \
                   vtb + (size_t)r * (Ncfg / 2) + ((k0) >> 1) + c); } \
    CP_COMMIT(); } while (0)

    float ofr[16][4];
#pragma unroll
    for (int nt = 0; nt < 16; nt++)
#pragma unroll
        for (int j = 0; j < 4; j++) ofr[nt][j] = 0.f;
    float m0 = NEG, m1 = NEG, l0 = 0.f, l1 = 0.f;

    const int wrow = 16 * wid + g;
    const int row0 = q0 + wrow;
    const int row1 = row0 + 8;
    const int nkv = 2 * (qb + 1);

    STAGE_K(0, 0);

    for (int kb = 0; kb < nkv; kb++) {
        __syncthreads();                    // Vs/Ps free (prev PV done)
        STAGE_V(kb * FKV);
        CP_WAIT(1);                         // K[kb] landed (V outstanding)
        __syncthreads();

        const uint32_t* Kc = smf + OFF_K + (kb & 1) * (FKV * LDK32);
        const uint32_t* Vc = smf + OFF_V;

        // S = Q K^T
        float sfr[8][4];
#pragma unroll
        for (int nt = 0; nt < 8; nt++)
#pragma unroll
            for (int j = 0; j < 4; j++) sfr[nt][j] = 0.f;

#pragma unroll
        for (int ks = 0; ks < 8; ks++) {
            const int col = ks * 8 + 2 * tg;
            uint2 qa = *(const uint2*)&Qs[(wrow)     * LDQ32 + col];
            uint2 qc = *(const uint2*)&Qs[(wrow + 8) * LDQ32 + col];
            uint32_t afr[4] = { qa.x, qc.x, qa.y, qc.y };
#pragma unroll
            for (int nt = 0; nt < 8; nt++) {
                uint2 kk = *(const uint2*)&Kc[(8 * nt + g) * LDK32 + col];
                mma_h(sfr[nt], afr, &kk.x);
            }
        }

        // scale + causal mask
#pragma unroll
        for (int nt = 0; nt < 8; nt++)
#pragma unroll
            for (int j = 0; j < 4; j++) sfr[nt][j] *= S2;

        const int k0 = kb * FKV;
        if (kb >= nkv - 2) {
#pragma unroll
            for (int nt = 0; nt < 8; nt++) {
                const int c0 = k0 + 8 * nt + 2 * tg;
                if (c0     > row0) sfr[nt][0] = NEG;
                if (c0 + 1 > row0) sfr[nt][1] = NEG;
                if (c0     > row1) sfr[nt][2] = NEG;
                if (c0 + 1 > row1) sfr[nt][3] = NEG;
            }
        }

        // online softmax
        float mx0 = NEG, mx1 = NEG;
#pragma unroll
        for (int nt = 0; nt < 8; nt++) {
            mx0 = fmaxf(mx0, fmaxf(sfr[nt][0], sfr[nt][1]));
            mx1 = fmaxf(mx1, fmaxf(sfr[nt][2], sfr[nt][3]));
        }
        mx0 = fmaxf(mx0, __shfl_xor_sync(0xffffffff, mx0, 1));
        mx0 = fmaxf(mx0, __shfl_xor_sync(0xffffffff, mx0, 2));
        mx1 = fmaxf(mx1, __shfl_xor_sync(0xffffffff, mx1, 1));
        mx1 = fmaxf(mx1, __shfl_xor_sync(0xffffffff, mx1, 2));

        const float mn0 = fmaxf(m0, mx0);
        const float mn1 = fmaxf(m1, mx1);
        const float scl0 = ex2(m0 - mn0);
        const float scl1 = ex2(m1 - mn1);

        float sum0 = 0.f, sum1 = 0.f;
#pragma unroll
        for (int nt = 0; nt < 8; nt++) {
            sfr[nt][0] = ex2(sfr[nt][0] - mn0);
            sfr[nt][1] = ex2(sfr[nt][1] - mn0);
            sfr[nt][2] = ex2(sfr[nt][2] - mn1);
            sfr[nt][3] = ex2(sfr[nt][3] - mn1);
            sum0 += sfr[nt][0] + sfr[nt][1];
            sum1 += sfr[nt][2] + sfr[nt][3];
        }
        sum0 += __shfl_xor_sync(0xffffffff, sum0, 1);
        sum0 += __shfl_xor_sync(0xffffffff, sum0, 2);
        sum1 += __shfl_xor_sync(0xffffffff, sum1, 1);
        sum1 += __shfl_xor_sync(0xffffffff, sum1, 2);

        l0 = l0 * scl0 + sum0;  m0 = mn0;
        l1 = l1 * scl1 + sum1;  m1 = mn1;

        // prefetch next K tile (covers PV)
        if (kb + 1 < nkv) STAGE_K((kb + 1) & 1, (kb + 1) * FKV);

        // store P as fp16 packed: nt-pair m -> u32 slots (m*8 + 2tg, +1)
#pragma unroll
        for (int m = 0; m < 4; m++) {
            uint2 p0 = { h2(sfr[2*m][0], sfr[2*m][1]), h2(sfr[2*m+1][0], sfr[2*m+1][1]) };
            uint2 p1 = { h2(sfr[2*m][2], sfr[2*m][3]), h2(sfr[2*m+1][2], sfr[2*m+1][3]) };
            *(uint2*)(Ps + (wrow)     * LDP32 + m * 8 + 2 * tg) = p0;
            *(uint2*)(Ps + (wrow + 8) * LDP32 + m * 8 + 2 * tg) = p1;
        }

        // rescale O
#pragma unroll
        for (int nt = 0; nt < 16; nt++) {
            ofr[nt][0] *= scl0; ofr[nt][1] *= scl0;
            ofr[nt][2] *= scl1; ofr[nt][3] *= scl1;
        }

        if (kb + 1 < nkv) { CP_WAIT(1); } else { CP_WAIT(0); }   // V[kb] done
        __syncthreads();                    // V + P visible

        // O += P V   (K = 64 -> 4 ks)
#pragma unroll
        for (int ks = 0; ks < 4; ks++) {
            const int col = ks * 8 + 2 * tg;
            uint2 pa = *(const uint2*)&Ps[(wrow)     * LDP32 + col];
            uint2 pc = *(const uint2*)&Ps[(wrow + 8) * LDP32 + col];
            uint32_t afr[4] = { pa.x, pc.x, pa.y, pc.y };
#pragma unroll
            for (int nt = 0; nt < 16; nt++) {
                uint2 vv = *(const uint2*)&Vc[(8 * nt + g) * LDV32 + col];
                mma_h(ofr[nt], afr, &vv.x);
            }
        }
    }

    // epilogue: write packed fp16 (nt-pair m -> u32 slots 2tg, 2tg+1)
    const float rl0 = 1.f / l0;
    const float rl1 = 1.f / l1;
    uint32_t* o0 = outp + (size_t)(b * Ncfg + row0) * (Ecfg / 2) + h * (Dcfg / 2);
    uint32_t* o1 = outp + (size_t)(b * Ncfg + row1) * (Ecfg / 2) + h * (Dcfg / 2);
#pragma unroll
    for (int m = 0; m < 8; m++) {
        uint2 v0 = { h2(ofr[2*m][0] * rl0, ofr[2*m][1] * rl0),
                     h2(ofr[2*m+1][0] * rl0, ofr[2*m+1][1] * rl0) };
        uint2 v1 = { h2(ofr[2*m][2] * rl1, ofr[2*m][3] * rl1),
                     h2(ofr[2*m+1][2] * rl1, ofr[2*m+1][3] * rl1) };
        *(uint2*)(o0 + m * 8 + 2 * tg) = v0;
        *(uint2*)(o1 + m * 8 + 2 * tg) = v1;
    }
}

// ---------------------------------------------------------------------------
extern "C" void kernel_launch(void* const* d_in, const int* in_sizes, int n_in,
                              void* d_out, int out_size)
{
    const float* x     = (const float*)d_in[0];
    const float* w_qkv = (const float*)d_in[1];
    const float* b_qkv = (const float*)d_in[2];
    const float* w_fc  = (const float*)d_in[3];
    const float* b_fc  = (const float*)d_in[4];
    float* out = (float*)d_out;

    float* qkv_ptr;  uint32_t *xp, *wqkvp, *wfcp, *kpp, *vtpp, *attnp;
    cudaGetSymbolAddress((void**)&qkv_ptr, g_qkv);
    cudaGetSymbolAddress((void**)&xp, g_xp);
    cudaGetSymbolAddress((void**)&wqkvp, g_wqkvp);
    cudaGetSymbolAddress((void**)&wfcp, g_wfcp);
    cudaGetSymbolAddress((void**)&kpp, g_kp);
    cudaGetSymbolAddress((void**)&vtpp, g_vtp);
    cudaGetSymbolAddress((void**)&attnp, g_attnp);

    cudaFuncSetAttribute(gemm_tc, cudaFuncAttributeMaxDynamicSharedMemorySize, GEMM_SMEM);
    cudaFuncSetAttribute(flash_h, cudaFuncAttributeMaxDynamicSharedMemorySize, FLASH_SMEM);

    // 0) pack x; transpose+pack weights (fp16)
    pack_f16_flat<<<(Mrows * Ecfg / 16 + 255) / 256, 256>>>(x, xp, (size_t)Mrows * Ecfg / 16);
    transpose_pack<<<dim3(Ecfg / 32, QKVN / 32, 1), 256>>>(w_qkv, QKVN, 0, wqkvp, 0, Ecfg / 2);
    transpose_pack<<<dim3(Ecfg / 32, Ecfg / 32, 1), 256>>>(w_fc, Ecfg, 0, wfcp, 0, Ecfg / 2);

    // 1) qkv = x @ w_qkv + b_qkv
    gemm_tc<<<dim3(QKVN / 128, Mrows / 128), 256, GEMM_SMEM>>>(
        xp, wqkvp, b_qkv, qkv_ptr, QKVN);

    // 2) pack K; transpose+pack V^T
    pack_k_kernel<<<Mrows * 8 / 256, 256>>>(qkv_ptr, kpp);
    transpose_pack<<<dim3(Ncfg / 32, Dcfg / 32, Bcfg), 256>>>(
        qkv_ptr + Ecfg + Dcfg, QKVN, (size_t)Ncfg * QKVN, vtpp, (size_t)Dcfg * Ncfg / 2, Ncfg / 2);

    // 3) flash attention -> packed fp16 attn
    flash_h<<<dim3(Ncfg / FQ, Hcfg, Bcfg), 256, FLASH_SMEM>>>(
        qkv_ptr, kpp, vtpp, attnp);

    // 4) out = attn @ w_fc + b_fc
    gemm_tc<<<dim3(Ecfg / 128, Mrows / 128), 256, GEMM_SMEM>>>(
        attnp, wfcp, b_fc, out, Ecfg);
}

// round 9
// speedup vs baseline: 12.9547x; 1.1136x over previous
#include <cuda_runtime.h>
#include <cuda_fp16.h>
#include <cstdint>

// Problem constants
#define Ecfg   2048
#define Hcfg   16
#define Dcfg   128
#define Bcfg   4
#define Ncfg   2048
#define QKVN   (Ecfg + 2 * Dcfg)   // 2304
#define Mrows  (Bcfg * Ncfg)       // 8192
#define GK     2048                // K of both GEMMs

// Scratch — all fp16 payloads are PLAIN row-major half pairs (u32 = half2)
__device__ float    g_qkv[(size_t)Mrows * QKVN];
__device__ uint32_t g_xp[(size_t)Mrows * Ecfg / 2];
__device__ uint32_t g_wqkvp[(size_t)QKVN * Ecfg / 2];
__device__ uint32_t g_wfcp[(size_t)Ecfg * Ecfg / 2];
__device__ uint32_t g_kp[(size_t)Mrows * Dcfg / 2];
__device__ uint32_t g_vtp[(size_t)Bcfg * Dcfg * Ncfg / 2];
__device__ uint32_t g_attnp[(size_t)Mrows * Ecfg / 2];

// ---------------------------------------------------------------------------
// helpers
// ---------------------------------------------------------------------------
__device__ __forceinline__ uint32_t h2(float lo, float hi) {
    __half2 h = __floats2half2_rn(lo, hi);
    return *(uint32_t*)&h;
}
__device__ __forceinline__ float ex2(float x) {
    float y;
    asm("ex2.approx.ftz.f32 %0, %1;" : "=f"(y) : "f"(x));
    return y;
}
__device__ __forceinline__ void mma_h(float* d, const uint32_t* a, const uint32_t* b) {
    asm volatile(
        "mma.sync.aligned.m16n8k16.row.col.f32.f16.f16.f32 "
        "{%0,%1,%2,%3}, {%4,%5,%6,%7}, {%8,%9}, {%0,%1,%2,%3};\n"
        : "+f"(d[0]), "+f"(d[1]), "+f"(d[2]), "+f"(d[3])
        : "r"(a[0]), "r"(a[1]), "r"(a[2]), "r"(a[3]), "r"(b[0]), "r"(b[1]));
}
__device__ __forceinline__ uint32_t smem_u32(const void* p) {
    uint32_t a;
    asm("{ .reg .u64 t; cvta.to.shared.u64 t, %1; cvt.u32.u64 %0, t; }" : "=r"(a) : "l"(p));
    return a;
}
#define LDSM4(r, addr) \
    asm volatile("ldmatrix.sync.aligned.m8n8.x4.shared.b16 {%0,%1,%2,%3}, [%4];" \
        : "=r"((r)[0]), "=r"((r)[1]), "=r"((r)[2]), "=r"((r)[3]) : "r"(addr))
#define CP_ASYNC16(sa, gp) \
    asm volatile("cp.async.cg.shared.global [%0], [%1], 16;" :: "r"(sa), "l"(gp))
#define CP_COMMIT() asm volatile("cp.async.commit_group;" ::: "memory")
#define CP_WAIT(n)  asm volatile("cp.async.wait_group %0;" :: "n"(n) : "memory")

// ---------------------------------------------------------------------------
// prep 1: flat fp32 -> plain fp16 pairs (16 floats -> 8 u32)
// ---------------------------------------------------------------------------
__global__ __launch_bounds__(256) void pack_f16_flat(
    const float* __restrict__ src, uint32_t* __restrict__ dst, size_t n16)
{
    size_t t = (size_t)blockIdx.x * 256 + threadIdx.x;
    if (t >= n16) return;
    const float4* s = (const float4*)(src + t * 16);
    float4 a = s[0], b = s[1], c = s[2], d = s[3];
    uint4 o0 = { h2(a.x, a.y), h2(a.z, a.w), h2(b.x, b.y), h2(b.z, b.w) };
    uint4 o1 = { h2(c.x, c.y), h2(c.z, c.w), h2(d.x, d.y), h2(d.z, d.w) };
    uint4* o = (uint4*)(dst + t * 8);
    o[0] = o0; o[1] = o1;
}

// ---------------------------------------------------------------------------
// prep 2: K slice of qkv -> plain fp16 [8192][64 u32]
// ---------------------------------------------------------------------------
__global__ __launch_bounds__(256) void pack_k_kernel(
    const float* __restrict__ qkv, uint32_t* __restrict__ kp)
{
    int t = blockIdx.x * 256 + threadIdx.x;       // 8192*8
    int row = t >> 3, grp = t & 7;
    const float4* s = (const float4*)(qkv + (size_t)row * QKVN + Ecfg + grp * 16);
    float4 a = s[0], b = s[1], c = s[2], d = s[3];
    uint4 o0 = { h2(a.x, a.y), h2(a.z, a.w), h2(b.x, b.y), h2(b.z, b.w) };
    uint4 o1 = { h2(c.x, c.y), h2(c.z, c.w), h2(d.x, d.y), h2(d.z, d.w) };
    uint4* o = (uint4*)(kp + (size_t)row * (Dcfg / 2) + grp * 8);
    o[0] = o0; o[1] = o1;
}

// ---------------------------------------------------------------------------
// prep 3: transpose + fp16: dst[j][i pairs] = src[i][j]
// ---------------------------------------------------------------------------
__global__ __launch_bounds__(256) void transpose_pack(
    const float* __restrict__ src, size_t sStride, size_t zsrc,
    uint32_t* __restrict__ dst, size_t zdst, int NIu)
{
    __shared__ float t[32][33];
    src += (size_t)blockIdx.z * zsrc;
    dst += (size_t)blockIdx.z * zdst;
    const int i0 = blockIdx.x * 32, j0 = blockIdx.y * 32;
    const int tid = threadIdx.x;
#pragma unroll
    for (int s = 0; s < 4; s++) {
        int ii = (tid >> 5) + s * 8, jj = tid & 31;
        t[ii][jj] = src[(size_t)(i0 + ii) * sStride + j0 + jj];
    }
    __syncthreads();
    if (tid < 64) {
        int jj = tid >> 1, grp = tid & 1;
        float v[16];
#pragma unroll
        for (int u = 0; u < 16; u++) v[u] = t[grp * 16 + u][jj];
        uint4 o0 = { h2(v[0], v[1]), h2(v[2], v[3]), h2(v[4], v[5]), h2(v[6], v[7]) };
        uint4 o1 = { h2(v[8], v[9]), h2(v[10], v[11]), h2(v[12], v[13]), h2(v[14], v[15]) };
        uint4* o = (uint4*)(dst + (size_t)(j0 + jj) * NIu + i0 / 2 + grp * 8);
        o[0] = o0; o[1] = o1;
    }
}

// ---------------------------------------------------------------------------
// fp16 GEMM, ldmatrix + 4-stage cp.async, one barrier/chunk, 2 CTAs/SM.
// BM=128, BN=128, BK=32; warp tile 32x64.
// smem row padded to 20 u32 (16B-unit pattern 5r mod 8 distinct -> LDSM
// conflict-free).
// ---------------------------------------------------------------------------
#define LDR    20
#define HSTGu  (128 * LDR)                 // 2560 u32
#define STGu2  (2 * HSTGu)                 // 5120 u32 / stage
#define NSTG   4
#define GEMM_SMEM (NSTG * STGu2 * 4)       // 81920 B

__global__ __launch_bounds__(256, 2) void gemm_tc(
    const uint32_t* __restrict__ A, const uint32_t* __restrict__ W,
    const float* __restrict__ bias, float* __restrict__ C,
    int Ncols)
{
    extern __shared__ uint32_t sm[];
    const uint32_t sbase = smem_u32(sm);

    const int tid = threadIdx.x;
    const int lane = tid & 31;
    const int wid = tid >> 5;
    const int warp_m = wid & 3;
    const int warp_n = wid >> 2;
    const int g = lane >> 2;
    const int tg = lane & 3;
    const int bm = blockIdx.y * 128;
    const int bn = blockIdx.x * 128;

    const int c_r = tid >> 2;               // 0..63 (+64)
    const int c_c = (tid & 3) * 4;          // u32 chunk col

    const uint32_t* asrc = A + (size_t)(bm + c_r) * (GK / 2) + c_c;
    const uint32_t* bsrc = W + (size_t)(bn + c_r) * (GK / 2) + c_c;

    // ldmatrix lane address bases (bytes)
    const int lr = lane & 7, lb1 = (lane >> 3) & 1, lb2 = (lane >> 4) & 1;
    const uint32_t a_base = sbase + (((warp_m * 32 + lr + lb1 * 8) * LDR) + lb2 * 4) * 4;
    const uint32_t b_base = sbase + ((HSTGu + (warp_n * 64 + lr + lb2 * 8) * LDR) + lb1 * 4) * 4;

    float acc[2][8][4];
#pragma unroll
    for (int mt = 0; mt < 2; mt++)
#pragma unroll
        for (int nt = 0; nt < 8; nt++)
#pragma unroll
            for (int j = 0; j < 4; j++) acc[mt][nt][j] = 0.f;

#define CPA_CHUNK(buf, k0) do { \
    const uint32_t so = sbase + (uint32_t)(buf) * (STGu2 * 4); \
    _Pragma("unroll") for (int s = 0; s < 2; s++) \
        CP_ASYNC16(so + (((c_r + 64 * s) * LDR) + c_c) * 4, \
                   asrc + (size_t)(64 * s) * (GK / 2) + ((k0) >> 1)); \
    _Pragma("unroll") for (int s = 0; s < 2; s++) \
        CP_ASYNC16(so + ((HSTGu + (c_r + 64 * s) * LDR + c_c) * 4), \
                   bsrc + (size_t)(64 * s) * (GK / 2) + ((k0) >> 1)); \
    CP_COMMIT(); \
    } while (0)

#define MMA_CHUNK(buf) do { \
    const uint32_t ab = a_base + (buf) * (STGu2 * 4); \
    const uint32_t bb = b_base + (buf) * (STGu2 * 4); \
    _Pragma("unroll") for (int ks = 0; ks < 2; ks++) { \
        uint32_t a0[4], a1[4]; \
        LDSM4(a0, ab + (ks * 8) * 4); \
        LDSM4(a1, ab + (320 + ks * 8) * 4); \
        _Pragma("unroll") for (int p = 0; p < 4; p++) { \
            uint32_t bq[4]; \
            LDSM4(bq, bb + (p * 320 + ks * 8) * 4); \
            mma_h(acc[0][2 * p],     a0, bq); \
            mma_h(acc[0][2 * p + 1], a0, bq + 2); \
            mma_h(acc[1][2 * p],     a1, bq); \
            mma_h(acc[1][2 * p + 1], a1, bq + 2); } \
    } } while (0)

    const int NCHUNK = GK / 32;             // 64
    CPA_CHUNK(0, 0);
    CPA_CHUNK(1, 32);
    CPA_CHUNK(2, 64);

#pragma unroll 4
    for (int c = 0; c < NCHUNK - 3; c++) {
        CP_WAIT(2);
        __syncthreads();
        CPA_CHUNK((c + 3) & 3, (c + 3) * 32);
        MMA_CHUNK(c & 3);
    }
    // tail: chunks NCHUNK-3 .. NCHUNK-1 (all already prefetched)
    CP_WAIT(2); __syncthreads(); MMA_CHUNK((NCHUNK - 3) & 3);
    CP_WAIT(1); __syncthreads(); MMA_CHUNK((NCHUNK - 2) & 3);
    CP_WAIT(0); __syncthreads(); MMA_CHUNK((NCHUNK - 1) & 3);

#pragma unroll
    for (int mt = 0; mt < 2; mt++) {
        const int row0 = bm + warp_m * 32 + mt * 16 + g;
#pragma unroll
        for (int nt = 0; nt < 8; nt++) {
            const int col = bn + warp_n * 64 + nt * 8 + 2 * tg;
            const float bx = __ldg(&bias[col]);
            const float by = __ldg(&bias[col + 1]);
            float2 v0 = { acc[mt][nt][0] + bx, acc[mt][nt][1] + by };
            float2 v1 = { acc[mt][nt][2] + bx, acc[mt][nt][3] + by };
            *(float2*)(C + (size_t)row0 * Ncols + col) = v0;
            *(float2*)(C + (size_t)(row0 + 8) * Ncols + col) = v1;
        }
    }
}

// ---------------------------------------------------------------------------
// Flash MQA (fp16 mma + ldmatrix). FQ=128, FKV=64; K double-buffered with
// compile-time slot (kb unrolled by 2); V prefetch overlaps S-phase.
// smem 104KB -> 2 CTAs/SM.
// ---------------------------------------------------------------------------
#define FQ     128
#define FKV    64
#define LDQK   68        // u32 row stride for Q/K (64 data + 4 pad)
#define LDVP   36        // u32 row stride for V^T / P (32 data + 4 pad)
#define OFF_Q  0
#define OFF_K  (FQ * LDQK)                        // 8704
#define OFF_V  (OFF_K + 2 * FKV * LDQK)           // 17408
#define OFF_P  (OFF_V + Dcfg * LDVP)              // 22016
#define FLASH_SMEM ((OFF_P + FQ * LDVP) * 4)      // 106496 B

__global__ __launch_bounds__(256, 2) void flash_h(
    const float* __restrict__ qkv, const uint32_t* __restrict__ kp,
    const uint32_t* __restrict__ vtp, uint32_t* __restrict__ outp)
{
    extern __shared__ uint32_t smf[];
    const uint32_t sbase = smem_u32(smf);
    uint32_t* Qs = smf + OFF_Q;

    const int tid = threadIdx.x;
    const int lane = tid & 31;
    const int wid = tid >> 5;
    const int g = lane >> 2;
    const int tg = lane & 3;

    const int qb = (gridDim.x - 1) - blockIdx.x;   // heavy blocks first
    const int h = blockIdx.y;
    const int b = blockIdx.z;
    const int q0 = qb * FQ;

    const float* qbase = qkv + (size_t)b * Ncfg * QKVN + h * Dcfg;
    const uint32_t* kpb = kp + (size_t)b * Ncfg * (Dcfg / 2);
    const uint32_t* vtb = vtp + (size_t)b * Dcfg * (Ncfg / 2);

    const float S2 = 0.08838834764831845f * 1.4426950408889634f;
    const float NEG = -1e30f;

    // Stage Q: fp32 -> fp16 pairs, plain layout
#pragma unroll
    for (int s = 0; s < 16; s++) {
        const int idx = s * 256 + tid;
        const int r = idx >> 5, c4 = (idx & 31) * 4;
        float4 v = *(const float4*)(qbase + (size_t)(q0 + r) * QKVN + c4);
        uint32_t* q = Qs + r * LDQK + (c4 >> 1);
        q[0] = h2(v.x, v.y);
        q[1] = h2(v.z, v.w);
    }

    // ldmatrix lane bases (bytes)
    const int lr = lane & 7, lb1 = (lane >> 3) & 1, lb2 = (lane >> 4) & 1;
    const uint32_t q_base  = sbase + (((16 * wid + lr + lb1 * 8) * LDQK) + lb2 * 4) * 4;
    const uint32_t k_base  = sbase + ((OFF_K + (lr + lb2 * 8) * LDQK) + lb1 * 4) * 4;
    const uint32_t v_base  = sbase + ((OFF_V + (lr + lb2 * 8) * LDVP) + lb1 * 4) * 4;
    const uint32_t pa_base = sbase + ((OFF_P + (16 * wid + lr + lb1 * 8) * LDVP) + lb2 * 4) * 4;
    uint32_t* Ps = smf + OFF_P;

    // FULL tile loads: K = 64 rows x 64 u32 (16KB), V = 128 rows x 32 u32 (16KB)
#define STAGE_K(slot_, k0) do { \
    _Pragma("unroll") for (int s = 0; s < 4; s++) { \
        const int idx = s * 256 + tid; \
        const int r = idx >> 4, c = (idx & 15) * 4; \
        CP_ASYNC16(sbase + (OFF_K + (slot_) * (FKV * LDQK) + r * LDQK + c) * 4, \
                   kpb + (size_t)((k0) + r) * (Dcfg / 2) + c); } \
    CP_COMMIT(); } while (0)

#define STAGE_V(k0) do { \
    _Pragma("unroll") for (int s = 0; s < 4; s++) { \
        const int idx = s * 256 + tid; \
        const int r = idx >> 3, c = (idx & 7) * 4; \
        CP_ASYNC16(sbase + (OFF_V + r * LDVP + c) * 4, \
                   vtb + (size_t)r * (Ncfg / 2) + ((k0) >> 1) + c); } \
    CP_COMMIT(); } while (0)

    float ofr[16][4];
#pragma unroll
    for (int nt = 0; nt < 16; nt++)
#pragma unroll
        for (int j = 0; j < 4; j++) ofr[nt][j] = 0.f;
    float m0 = NEG, m1 = NEG, l0 = 0.f, l1 = 0.f;

    const int wrow = 16 * wid + g;
    const int row0 = q0 + wrow;
    const int row1 = row0 + 8;
    const int nkv = 2 * (qb + 1);

    STAGE_K(0, 0);

#define FLASH_BODY(kb, SLOT) do { \
    __syncthreads(); \
    STAGE_V((kb) * FKV); \
    CP_WAIT(1); \
    __syncthreads(); \
    float sfr[8][4]; \
    _Pragma("unroll") for (int nt = 0; nt < 8; nt++) \
        _Pragma("unroll") for (int j = 0; j < 4; j++) sfr[nt][j] = 0.f; \
    _Pragma("unroll") for (int ks = 0; ks < 8; ks++) { \
        uint32_t aq[4]; \
        LDSM4(aq, q_base + ks * 32); \
        _Pragma("unroll") for (int p = 0; p < 4; p++) { \
            uint32_t bq[4]; \
            LDSM4(bq, k_base + ((SLOT) * (FKV * LDQK) + p * 16 * LDQK + ks * 8) * 4); \
            mma_h(sfr[2 * p],     aq, bq); \
            mma_h(sfr[2 * p + 1], aq, bq + 2); } \
    } \
    _Pragma("unroll") for (int nt = 0; nt < 8; nt++) \
        _Pragma("unroll") for (int j = 0; j < 4; j++) sfr[nt][j] *= S2; \
    const int k0m = (kb) * FKV; \
    if ((kb) >= nkv - 2) { \
        _Pragma("unroll") for (int nt = 0; nt < 8; nt++) { \
            const int c0 = k0m + 8 * nt + 2 * tg; \
            if (c0     > row0) sfr[nt][0] = NEG; \
            if (c0 + 1 > row0) sfr[nt][1] = NEG; \
            if (c0     > row1) sfr[nt][2] = NEG; \
            if (c0 + 1 > row1) sfr[nt][3] = NEG; } \
    } \
    float mx0 = NEG, mx1 = NEG; \
    _Pragma("unroll") for (int nt = 0; nt < 8; nt++) { \
        mx0 = fmaxf(mx0, fmaxf(sfr[nt][0], sfr[nt][1])); \
        mx1 = fmaxf(mx1, fmaxf(sfr[nt][2], sfr[nt][3])); } \
    mx0 = fmaxf(mx0, __shfl_xor_sync(0xffffffff, mx0, 1)); \
    mx0 = fmaxf(mx0, __shfl_xor_sync(0xffffffff, mx0, 2)); \
    mx1 = fmaxf(mx1, __shfl_xor_sync(0xffffffff, mx1, 1)); \
    mx1 = fmaxf(mx1, __shfl_xor_sync(0xffffffff, mx1, 2)); \
    const float mn0 = fmaxf(m0, mx0); \
    const float mn1 = fmaxf(m1, mx1); \
    const float scl0 = ex2(m0 - mn0); \
    const float scl1 = ex2(m1 - mn1); \
    float sum0 = 0.f, sum1 = 0.f; \
    _Pragma("unroll") for (int nt = 0; nt < 8; nt++) { \
        sfr[nt][0] = ex2(sfr[nt][0] - mn0); \
        sfr[nt][1] = ex2(sfr[nt][1] - mn0); \
        sfr[nt][2] = ex2(sfr[nt][2] - mn1); \
        sfr[nt][3] = ex2(sfr[nt][3] - mn1); \
        sum0 += sfr[nt][0] + sfr[nt][1]; \
        sum1 += sfr[nt][2] + sfr[nt][3]; } \
    sum0 += __shfl_xor_sync(0xffffffff, sum0, 1); \
    sum0 += __shfl_xor_sync(0xffffffff, sum0, 2); \
    sum1 += __shfl_xor_sync(0xffffffff, sum1, 1); \
    sum1 += __shfl_xor_sync(0xffffffff, sum1, 2); \
    l0 = l0 * scl0 + sum0;  m0 = mn0; \
    l1 = l1 * scl1 + sum1;  m1 = mn1; \
    if ((kb) + 1 < nkv) STAGE_K((SLOT) ^ 1, ((kb) + 1) * FKV); \
    _Pragma("unroll") for (int nt = 0; nt < 8; nt++) { \
        Ps[(wrow)     * LDVP + 4 * nt + tg] = h2(sfr[nt][0], sfr[nt][1]); \
        Ps[(wrow + 8) * LDVP + 4 * nt + tg] = h2(sfr[nt][2], sfr[nt][3]); } \
    _Pragma("unroll") for (int nt = 0; nt < 16; nt++) { \
        ofr[nt][0] *= scl0; ofr[nt][1] *= scl0; \
        ofr[nt][2] *= scl1; ofr[nt][3] *= scl1; } \
    if ((kb) + 1 < nkv) { CP_WAIT(1); } else { CP_WAIT(0); } \
    __syncthreads(); \
    _Pragma("unroll") for (int ks = 0; ks < 4; ks++) { \
        uint32_t ap[4]; \
        LDSM4(ap, pa_base + ks * 32); \
        _Pragma("unroll") for (int p = 0; p < 8; p++) { \
            uint32_t bv[4]; \
            LDSM4(bv, v_base + (p * 16 * LDVP + ks * 8) * 4); \
            mma_h(ofr[2 * p],     ap, bv); \
            mma_h(ofr[2 * p + 1], ap, bv + 2); } \
    } } while (0)

    for (int kb2 = 0; kb2 < nkv; kb2 += 2) {
        FLASH_BODY(kb2, 0);
        FLASH_BODY(kb2 + 1, 1);
    }

    // epilogue: plain fp16 pairs
    const float rl0 = 1.f / l0;
    const float rl1 = 1.f / l1;
    uint32_t* o0 = outp + (size_t)(b * Ncfg + row0) * (Ecfg / 2) + h * (Dcfg / 2);
    uint32_t* o1 = outp + (size_t)(b * Ncfg + row1) * (Ecfg / 2) + h * (Dcfg / 2);
#pragma unroll
    for (int nt = 0; nt < 16; nt++) {
        o0[4 * nt + tg] = h2(ofr[nt][0] * rl0, ofr[nt][1] * rl0);
        o1[4 * nt + tg] = h2(ofr[nt][2] * rl1, ofr[nt][3] * rl1);
    }
}

// ---------------------------------------------------------------------------
extern "C" void kernel_launch(void* const* d_in, const int* in_sizes, int n_in,
                              void* d_out, int out_size)
{
    const float* x     = (const float*)d_in[0];
    const float* w_qkv = (const float*)d_in[1];
    const float* b_qkv = (const float*)d_in[2];
    const float* w_fc  = (const float*)d_in[3];
    const float* b_fc  = (const float*)d_in[4];
    float* out = (float*)d_out;

    float* qkv_ptr;  uint32_t *xp, *wqkvp, *wfcp, *kpp, *vtpp, *attnp;
    cudaGetSymbolAddress((void**)&qkv_ptr, g_qkv);
    cudaGetSymbolAddress((void**)&xp, g_xp);
    cudaGetSymbolAddress((void**)&wqkvp, g_wqkvp);
    cudaGetSymbolAddress((void**)&wfcp, g_wfcp);
    cudaGetSymbolAddress((void**)&kpp, g_kp);
    cudaGetSymbolAddress((void**)&vtpp, g_vtp);
    cudaGetSymbolAddress((void**)&attnp, g_attnp);

    cudaFuncSetAttribute(gemm_tc, cudaFuncAttributeMaxDynamicSharedMemorySize, GEMM_SMEM);
    cudaFuncSetAttribute(flash_h, cudaFuncAttributeMaxDynamicSharedMemorySize, FLASH_SMEM);

    // 0) pack x; transpose weights (fp16)
    pack_f16_flat<<<(Mrows * Ecfg / 16 + 255) / 256, 256>>>(x, xp, (size_t)Mrows * Ecfg / 16);
    transpose_pack<<<dim3(Ecfg / 32, QKVN / 32, 1), 256>>>(w_qkv, QKVN, 0, wqkvp, 0, Ecfg / 2);
    transpose_pack<<<dim3(Ecfg / 32, Ecfg / 32, 1), 256>>>(w_fc, Ecfg, 0, wfcp, 0, Ecfg / 2);

    // 1) qkv = x @ w_qkv + b_qkv
    gemm_tc<<<dim3(QKVN / 128, Mrows / 128), 256, GEMM_SMEM>>>(
        xp, wqkvp, b_qkv, qkv_ptr, QKVN);

    // 2) pack K; transpose V^T
    pack_k_kernel<<<Mrows * 8 / 256, 256>>>(qkv_ptr, kpp);
    transpose_pack<<<dim3(Ncfg / 32, Dcfg / 32, Bcfg), 256>>>(
        qkv_ptr + Ecfg + Dcfg, QKVN, (size_t)Ncfg * QKVN, vtpp, (size_t)Dcfg * Ncfg / 2, Ncfg / 2);

    // 3) flash attention -> fp16 attn
    flash_h<<<dim3(Ncfg / FQ, Hcfg, Bcfg), 256, FLASH_SMEM>>>(
        qkv_ptr, kpp, vtpp, attnp);

    // 4) out = attn @ w_fc + b_fc
    gemm_tc<<<dim3(Ecfg / 128, Mrows / 128), 256, GEMM_SMEM>>>(
        attnp, wfcp, b_fc, out, Ecfg);
}